// round 13
// baseline (speedup 1.0000x reference)
#include <cuda_runtime.h>
#include <cuda_bf16.h>
#include <math.h>

// ---------------- scratch (static device globals; no allocation) ----------------
__device__ float g_lbuf[256 * 22 * 4096];   // log-eig planes, layout [n][ch][pos]
__device__ float g_h2[256 * 32 * 4096];     // h2, layout [n][ch][pos]
__device__ float g_eusum[256 * 22];
__device__ float g_eusq[256 * 22];
__device__ float g_h2sum[256 * 32];
__device__ float g_h2sq[256 * 32];
__device__ float g_cov3[256 * 32];
__device__ float g_em3[10];

#define MAXSWEEPS 10
#define UPAD 68   // U column stride (floats); 16B-aligned

typedef unsigned long long ull;

// ---- packed f32x2 helpers (sm_103a; ptxas only emits FFMA2 via PTX) ----
__device__ __forceinline__ ull f2mul(ull a, ull b) {
    ull d; asm("mul.rn.f32x2 %0, %1, %2;" : "=l"(d) : "l"(a), "l"(b)); return d;
}
__device__ __forceinline__ ull f2fma(ull a, ull b, ull c) {
    ull d; asm("fma.rn.f32x2 %0, %1, %2, %3;" : "=l"(d) : "l"(a), "l"(b), "l"(c)); return d;
}
__device__ __forceinline__ ull f2pack(float lo, float hi) {
    ull d; asm("mov.b64 %0, {%1, %2};" : "=l"(d) : "f"(lo), "f"(hi)); return d;
}
__device__ __forceinline__ float2 f2unpack(ull v) {
    float lo, hi; asm("mov.b64 {%0, %1}, %2;" : "=f"(lo), "=f"(hi) : "l"(v));
    return make_float2(lo, hi);
}

// a column fragment held by one lane: 8 floats = 4 f32x2
struct Col { ull v[4]; };

__device__ __forceinline__ float col_dot(const Col& a, const Col& b) {
    ull acc = f2mul(a.v[0], b.v[0]);
    acc = f2fma(a.v[1], b.v[1], acc);
    acc = f2fma(a.v[2], b.v[2], acc);
    acc = f2fma(a.v[3], b.v[3], acc);
    float2 t = f2unpack(acc);
    return t.x + t.y;
}
// ca*a + cb*b
__device__ __forceinline__ Col col_comb(const Col& a, const Col& b, float ca, float cb) {
    ull CA = f2pack(ca, ca), CB = f2pack(cb, cb);
    Col r;
    r.v[0] = f2fma(a.v[0], CA, f2mul(b.v[0], CB));
    r.v[1] = f2fma(a.v[1], CA, f2mul(b.v[1], CB));
    r.v[2] = f2fma(a.v[2], CA, f2mul(b.v[2], CB));
    r.v[3] = f2fma(a.v[3], CA, f2mul(b.v[3], CB));
    return r;
}
__device__ __forceinline__ Col col_load(const float* base, int ql) {
    const ulonglong2* p = (const ulonglong2*)base;
    ulonglong2 a = p[ql], b = p[ql + 8];
    Col c; c.v[0] = a.x; c.v[1] = a.y; c.v[2] = b.x; c.v[3] = b.y;
    return c;
}
__device__ __forceinline__ void col_store(float* base, int ql, const Col& c) {
    ulonglong2* p = (ulonglong2*)base;
    p[ql]     = make_ulonglong2(c.v[0], c.v[1]);
    p[ql + 8] = make_ulonglong2(c.v[2], c.v[3]);
}

// ---------------- K0: init accumulators + scalar-embedding MLP ----------------
__global__ void init_kernel(const void* __restrict__ Mraw,
                            const float* __restrict__ we1, const float* __restrict__ be1,
                            const float* __restrict__ we2, const float* __restrict__ be2,
                            const float* __restrict__ we3, const float* __restrict__ be3,
                            const float* __restrict__ ln_g, const float* __restrict__ ln_b) {
    const int t = threadIdx.x;  // 256 threads, 1 block
    for (int i = t; i < 256 * 32; i += 256) {
        g_h2sum[i] = 0.f; g_h2sq[i] = 0.f; g_cov3[i] = 0.f;
    }
    __shared__ float md[2];
    __shared__ float em[10], emln[10], em2[100];
    __shared__ float mu_s, isd_s;
    if (t == 0) {
        int mi = *(const int*)Mraw;
        float Mv = (mi > 0 && mi < 100000000) ? (float)mi : __int_as_float(mi);
        md[0] = Mv / 500.0f;
        md[1] = 64.0f / 100.0f;
    }
    __syncthreads();
    if (t < 10) em[t] = md[0] * we1[t] + md[1] * we1[10 + t] + be1[t];
    __syncthreads();
    if (t == 0) {
        float s = 0.f, s2 = 0.f;
        for (int j = 0; j < 10; ++j) { s += em[j]; s2 += em[j] * em[j]; }
        float mu = s * 0.1f;
        float var = fmaxf(s2 * 0.1f - mu * mu, 0.f);
        mu_s = mu;
        isd_s = rsqrtf(var + 1e-3f);   // keras LN: eps inside sqrt
    }
    __syncthreads();
    if (t < 10) emln[t] = (em[t] - mu_s) * isd_s * ln_g[t] + ln_b[t];
    __syncthreads();
    if (t < 100) {
        float a = be2[t];
        for (int j = 0; j < 10; ++j) a += emln[j] * we2[j * 100 + t];
        em2[t] = fmaxf(a, 0.f);
    }
    __syncthreads();
    if (t < 10) {
        float a = be3[t];
        for (int k = 0; k < 100; ++k) a += em2[k] * we3[k * 10 + t];
        g_em3[t] = em[t] + a;
    }
}

// ---------------- K1: shifted one-sided Jacobi, register-resident odd-even --------
// U = A + sigma*I (PD). 32 slots (quarter-warps) hold 2 columns each in REGISTERS.
// Odd-even transposition schedule with unconditional swap: 64 steps visit all
// C(64,2) pairs. Even steps: in-slot pair (zero smem). Odd steps: exchange with
// neighbor slots via staging (overlaid on U). Reconstruction is permutation-
// invariant so column identities are never tracked.
__global__ __launch_bounds__(256, 5) void eig_kernel(const float* __restrict__ x) {
    __shared__ __align__(16) float U[64 * UPAD];
    __shared__ float nrm[64];
    __shared__ float gsc[64];
    __shared__ float wred[16];
    __shared__ float sig_s, sig2_s;
    __shared__ int conv_s;

    const int t = threadIdx.x;
    const int warp = t >> 5, lane = t & 31;
    const int b = blockIdx.x;      // n*22 + ch
    const float* src = x + (size_t)b * 4096;

    // load plane (coalesced) into U column-major
    #pragma unroll
    for (int it = 0; it < 16; ++it) {
        int id = t + 256 * it;
        int r_ = id >> 6, c_ = id & 63;
        U[c_ * UPAD + r_] = src[id];
    }
    __syncthreads();
    // symmetrize in smem + Frobenius norm^2
    float fn = 0.f;
    #pragma unroll
    for (int it = 0; it < 16; ++it) {
        int id = t + 256 * it;
        int i = id >> 6, j = id & 63;
        if (i < j) {
            float a = 0.5f * (U[i * UPAD + j] + U[j * UPAD + i]);
            U[i * UPAD + j] = a; U[j * UPAD + i] = a;
            fn += 2.f * a * a;
        } else if (i == j) {
            float d = U[i * UPAD + i];
            fn += d * d;
        }
    }
    #pragma unroll
    for (int off = 16; off; off >>= 1) fn += __shfl_xor_sync(0xffffffffu, fn, off);
    if (lane == 0) wred[warp] = fn;
    __syncthreads();
    if (t == 0) {
        float s = 0.f;
        for (int i = 0; i < 8; ++i) s += wred[i];
        sig2_s = s;
        sig_s = sqrtf(s);
        conv_s = 0;
    }
    __syncthreads();
    const float sigma = sig_s;
    if (t < 64) U[t * UPAD + t] += sigma;   // shift: U = A + sigma*I  (PD)
    __syncthreads();
    // initial column sq-norms
    if (t < 64) {
        const float* uc = U + t * UPAD;
        float s = 0.f;
        #pragma unroll 8
        for (int r_ = 0; r_ < 64; ++r_) { float v = uc[r_]; s += v * v; }
        nrm[t] = s;
    }
    __syncthreads();

    const float skipthr = 4e-5f * sig2_s + 1e-30f;
    const float convthr = 4e-4f * sig2_s + 1e-30f;

    const int ql = lane & 7;                 // lane within quarter
    const int sQ = (warp << 2) | (lane >> 3);  // slot 0..31

    // load this slot's two columns into registers
    Col colL = col_load(U + (2 * sQ) * UPAD, ql);
    Col colR = col_load(U + (2 * sQ + 1) * UPAD, ql);
    float nL = nrm[2 * sQ], nR = nrm[2 * sQ + 1];
    __syncthreads();   // everyone done reading U before staging overwrites it

    float* stag = U;   // staging: position-indexed, 64 floats per column

    for (int sweep = 0; sweep < MAXSWEEPS; ++sweep) {
        float swmax = 0.f;
        for (int half = 0; half < 32; ++half) {
            // ---- even step: internal pair (p = colL @pos 2s, q = colR @pos 2s+1)
            {
                float spq = col_dot(colL, colR);
                #pragma unroll
                for (int off = 4; off; off >>= 1)
                    spq += __shfl_xor_sync(0xffffffffu, spq, off);
                swmax = fmaxf(swmax, fabsf(spq));
                if (fabsf(spq) > skipthr) {
                    float tau = (nR - nL) / (2.f * spq);
                    float tt = copysignf(1.f, tau) / (fabsf(tau) + sqrtf(1.f + tau * tau));
                    float c = rsqrtf(1.f + tt * tt);
                    float s = tt * c;
                    float cc = c * c, ss = s * s, cs2 = 2.f * c * s * spq;
                    Col nl = col_comb(colL, colR, s, c);    // q' = s*p + c*q
                    Col nr = col_comb(colL, colR, c, -s);   // p' = c*p - s*q
                    float nLn = ss * nL + cc * nR + cs2;
                    float nRn = cc * nL + ss * nR - cs2;
                    colL = nl; colR = nr; nL = nLn; nR = nRn;
                } else {   // pure swap
                    Col tc = colL; colL = colR; colR = tc;
                    float tn = nL; nL = nR; nR = tn;
                }
            }
            // ---- odd step: external pairs (R_s @2s+1 with L_{s+1} @2s+2)
            {
                col_store(stag + (2 * sQ) * 64, ql, colL);
                col_store(stag + (2 * sQ + 1) * 64, ql, colR);
                if (ql == 0) { nrm[2 * sQ] = nL; nrm[2 * sQ + 1] = nR; }
                __syncthreads();
                // L side: pair (p = stag[2s-1], q = colL)
                {
                    int ppos = (sQ > 0) ? (2 * sQ - 1) : 0;
                    Col pc = col_load(stag + ppos * 64, ql);
                    float nP = nrm[ppos];
                    float spq = col_dot(pc, colL);
                    #pragma unroll
                    for (int off = 4; off; off >>= 1)
                        spq += __shfl_xor_sync(0xffffffffu, spq, off);
                    if (sQ > 0) {
                        swmax = fmaxf(swmax, fabsf(spq));
                        if (fabsf(spq) > skipthr) {
                            float tau = (nL - nP) / (2.f * spq);
                            float tt = copysignf(1.f, tau) / (fabsf(tau) + sqrtf(1.f + tau * tau));
                            float c = rsqrtf(1.f + tt * tt);
                            float s = tt * c;
                            float cc = c * c, ss = s * s, cs2 = 2.f * c * s * spq;
                            colL = col_comb(pc, colL, c, -s);   // p' stays at pos 2s
                            nL = cc * nP + ss * nL - cs2;
                        } else { colL = pc; nL = nP; }          // pure swap
                    }
                }
                // R side: pair (p = colR, q = stag[2s+2])
                {
                    int qpos = (sQ < 31) ? (2 * sQ + 2) : 63;
                    Col qc = col_load(stag + qpos * 64, ql);
                    float nQ = nrm[qpos];
                    float spq = col_dot(colR, qc);
                    #pragma unroll
                    for (int off = 4; off; off >>= 1)
                        spq += __shfl_xor_sync(0xffffffffu, spq, off);
                    if (sQ < 31) {
                        swmax = fmaxf(swmax, fabsf(spq));
                        if (fabsf(spq) > skipthr) {
                            float tau = (nQ - nR) / (2.f * spq);
                            float tt = copysignf(1.f, tau) / (fabsf(tau) + sqrtf(1.f + tau * tau));
                            float c = rsqrtf(1.f + tt * tt);
                            float s = tt * c;
                            float cc = c * c, ss = s * s, cs2 = 2.f * c * s * spq;
                            colR = col_comb(colR, qc, s, c);    // q' stays at pos 2s+1
                            nR = ss * nR + cc * nQ + cs2;
                        } else { colR = qc; nR = nQ; }          // pure swap
                    }
                }
                __syncthreads();   // staging reusable next external step
            }
        }
        // convergence: swmax is slot-uniform; merge quarters, then block
        swmax = fmaxf(swmax, __shfl_xor_sync(0xffffffffu, swmax, 8));
        swmax = fmaxf(swmax, __shfl_xor_sync(0xffffffffu, swmax, 16));
        if (lane == 0) wred[warp] = swmax;
        __syncthreads();
        if (t == 0) {
            float m = wred[0];
            for (int i = 1; i < 8; ++i) m = fmaxf(m, wred[i]);
            conv_s = (m < convthr) ? 1 : 0;
        }
        __syncthreads();
        if (conv_s) break;
    }

    // write columns back to U (any order; reconstruction is permutation-invariant)
    col_store(U + (2 * sQ) * UPAD, ql, colL);
    col_store(U + (2 * sQ + 1) * UPAD, ql, colR);
    __syncthreads();

    // exact column norms (double), lambda = ||u|| - sigma, scale g = f/||u||^2
    if (t < 64) {
        const float* uc = U + t * UPAD;
        double s = 0.0;
        #pragma unroll 8
        for (int r_ = 0; r_ < 64; ++r_) { double v = (double)uc[r_]; s += v * v; }
        double rho = sqrt(s);
        float lam = (float)(rho - (double)sigma);
        float f = logf(fmaxf(lam, 1e-4f));
        gsc[t] = (float)((double)f / s);
    }
    __syncthreads();

    // L[i][j] = sum_m gsc[m] * U[m][i] * U[m][j]; thread: row i0 x 16-col chunk
    const int i0 = t >> 2;
    const int j0 = (t & 3) << 4;
    float acc16[16];
    #pragma unroll
    for (int jj = 0; jj < 16; ++jj) acc16[jj] = 0.f;
    #pragma unroll 4
    for (int m = 0; m < 64; ++m) {
        float a = gsc[m] * U[m * UPAD + i0];
        const float* ur = U + m * UPAD + j0;
        #pragma unroll
        for (int jj = 0; jj < 16; ++jj) acc16[jj] += a * ur[jj];
    }
    float lsum = 0.f, lsq = 0.f;
    float* dst = g_lbuf + (size_t)b * 4096;
    #pragma unroll
    for (int jj = 0; jj < 16; ++jj) {
        float v = acc16[jj];
        dst[i0 * 64 + j0 + jj] = v;
        lsum += v; lsq += v * v;
    }
    #pragma unroll
    for (int off = 16; off; off >>= 1) {
        lsum += __shfl_down_sync(0xffffffffu, lsum, off);
        lsq  += __shfl_down_sync(0xffffffffu, lsq, off);
    }
    if (lane == 0) { wred[warp] = lsum; wred[8 + warp] = lsq; }
    __syncthreads();
    if (t == 0) {
        float s1 = 0.f, s2 = 0.f;
        for (int i = 0; i < 8; ++i) { s1 += wred[i]; s2 += wred[8 + i]; }
        g_eusum[b] = s1;
        g_eusq[b]  = s2;
    }
}

// ---------------- K2: block 1  (matnorm(eu) @ w2 -> relu -> @w3 + eu) ----------------
__global__ __launch_bounds__(128) void dense1_kernel(const float* __restrict__ w2, const float* __restrict__ b2,
                                                     const float* __restrict__ w3, const float* __restrict__ b3) {
    const int t = threadIdx.x;
    const int n = blockIdx.y;
    const int pos = blockIdx.x * 128 + t;
    __shared__ float sw2[1024], sw3[1024], sb2[32], sb3[32];
    __shared__ float meanS[22], isdS[22], em3S[10];
    __shared__ float acc1[32], acc2[32];
    for (int i = t; i < 1024; i += 128) { sw2[i] = w2[i]; sw3[i] = w3[i]; }
    if (t < 32) { sb2[t] = b2[t]; sb3[t] = b3[t]; acc1[t] = 0.f; acc2[t] = 0.f; }
    if (t < 22) {
        float mu = g_eusum[n * 22 + t] * (1.f / 4096.f);
        float var = fmaxf(g_eusq[n * 22 + t] * (1.f / 4096.f) - mu * mu, 0.f);
        meanS[t] = mu;
        isdS[t] = 1.f / fmaxf(sqrtf(var), 1e-3f);   // matnorm: clamp OUTSIDE sqrt
    }
    if (t < 10) em3S[t] = g_em3[t];
    __syncthreads();

    float eu[32];
    #pragma unroll
    for (int c = 0; c < 22; ++c) eu[c] = g_lbuf[((size_t)n * 22 + c) * 4096 + pos];
    #pragma unroll
    for (int c = 22; c < 32; ++c) eu[c] = em3S[c - 22];
    float mt[22];
    #pragma unroll
    for (int c = 0; c < 22; ++c) mt[c] = (eu[c] - meanS[c]) * isdS[c];
    // matnorm of the constant embedding channels is exactly 0 (std clamped), so skip c>=22
    float res[32];
    #pragma unroll
    for (int o = 0; o < 32; ++o) {
        float a = sb2[o];
        #pragma unroll
        for (int c = 0; c < 22; ++c) a += mt[c] * sw2[c * 32 + o];
        res[o] = fmaxf(a, 0.f);
    }
    #pragma unroll
    for (int o = 0; o < 32; ++o) {
        float a = sb3[o];
        #pragma unroll
        for (int c = 0; c < 32; ++c) a += res[c] * sw3[c * 32 + o];
        float h = eu[o] + a;
        g_h2[((size_t)n * 32 + o) * 4096 + pos] = h;
        float s1 = h, s2 = h * h;
        #pragma unroll
        for (int off = 16; off; off >>= 1) {
            s1 += __shfl_down_sync(0xffffffffu, s1, off);
            s2 += __shfl_down_sync(0xffffffffu, s2, off);
        }
        if ((t & 31) == 0) { atomicAdd(&acc1[o], s1); atomicAdd(&acc2[o], s2); }
    }
    __syncthreads();
    if (t < 32) {
        atomicAdd(&g_h2sum[n * 32 + t], acc1[t]);
        atomicAdd(&g_h2sq[n * 32 + t], acc2[t]);
    }
}

// ---------------- K3: block 2  (matnorm(h2) @ w4 -> relu -> @w5 + h2, mean) ----------------
__global__ __launch_bounds__(128) void dense2_kernel(const float* __restrict__ w4, const float* __restrict__ b4,
                                                     const float* __restrict__ w5, const float* __restrict__ b5) {
    const int t = threadIdx.x;
    const int n = blockIdx.y;
    const int pos = blockIdx.x * 128 + t;
    __shared__ float sw4[1024], sw5[1024], sb4[32], sb5[32];
    __shared__ float meanS[32], isdS[32];
    __shared__ float acc1[32];
    for (int i = t; i < 1024; i += 128) { sw4[i] = w4[i]; sw5[i] = w5[i]; }
    if (t < 32) {
        sb4[t] = b4[t]; sb5[t] = b5[t]; acc1[t] = 0.f;
        float mu = g_h2sum[n * 32 + t] * (1.f / 4096.f);
        float var = fmaxf(g_h2sq[n * 32 + t] * (1.f / 4096.f) - mu * mu, 0.f);
        meanS[t] = mu;
        isdS[t] = 1.f / fmaxf(sqrtf(var), 1e-3f);
    }
    __syncthreads();

    float hv[32];
    #pragma unroll
    for (int c = 0; c < 32; ++c) hv[c] = g_h2[((size_t)n * 32 + c) * 4096 + pos];
    float mt[32];
    #pragma unroll
    for (int c = 0; c < 32; ++c) mt[c] = (hv[c] - meanS[c]) * isdS[c];
    float res[32];
    #pragma unroll
    for (int o = 0; o < 32; ++o) {
        float a = sb4[o];
        #pragma unroll
        for (int c = 0; c < 32; ++c) a += mt[c] * sw4[c * 32 + o];
        res[o] = fmaxf(a, 0.f);
    }
    #pragma unroll
    for (int o = 0; o < 32; ++o) {
        float a = sb5[o];
        #pragma unroll
        for (int c = 0; c < 32; ++c) a += res[c] * sw5[c * 32 + o];
        float h = hv[o] + a;
        float s1 = h;
        #pragma unroll
        for (int off = 16; off; off >>= 1) s1 += __shfl_down_sync(0xffffffffu, s1, off);
        if ((t & 31) == 0) atomicAdd(&acc1[o], s1);
    }
    __syncthreads();
    if (t < 32) atomicAdd(&g_cov3[n * 32 + t], acc1[t]);
}

// ---------------- K4: head (cov3 @ w -> softmax) ----------------
__global__ void head_kernel(const float* __restrict__ w, float* __restrict__ out) {
    const int n = threadIdx.x;  // 256 threads
    float c[32];
    #pragma unroll
    for (int ch = 0; ch < 32; ++ch) c[ch] = g_cov3[n * 32 + ch] * (1.f / 4096.f);
    float lg[7];
    #pragma unroll
    for (int cls = 0; cls < 7; ++cls) {
        float a = 0.f;
        #pragma unroll
        for (int ch = 0; ch < 32; ++ch) a += c[ch] * w[ch * 7 + cls];
        lg[cls] = a;
    }
    float mx = lg[0];
    #pragma unroll
    for (int cls = 1; cls < 7; ++cls) mx = fmaxf(mx, lg[cls]);
    float sum = 0.f;
    #pragma unroll
    for (int cls = 0; cls < 7; ++cls) { lg[cls] = expf(lg[cls] - mx); sum += lg[cls]; }
    float inv = 1.f / sum;
    #pragma unroll
    for (int cls = 0; cls < 7; ++cls) out[n * 7 + cls] = lg[cls] * inv;
}

// ---------------- launch ----------------
extern "C" void kernel_launch(void* const* d_in, const int* in_sizes, int n_in,
                              void* d_out, int out_size) {
    const float* x   = (const float*)d_in[0];
    const void*  M   = d_in[1];
    const float* w   = (const float*)d_in[2];
    const float* w2  = (const float*)d_in[3];
    const float* b2  = (const float*)d_in[4];
    const float* w3  = (const float*)d_in[5];
    const float* b3  = (const float*)d_in[6];
    const float* w4  = (const float*)d_in[7];
    const float* b4  = (const float*)d_in[8];
    const float* w5  = (const float*)d_in[9];
    const float* b5  = (const float*)d_in[10];
    const float* we1 = (const float*)d_in[11];
    const float* be1 = (const float*)d_in[12];
    const float* we2 = (const float*)d_in[13];
    const float* be2 = (const float*)d_in[14];
    const float* we3 = (const float*)d_in[15];
    const float* be3 = (const float*)d_in[16];
    const float* lng = (const float*)d_in[17];
    const float* lnb = (const float*)d_in[18];

    init_kernel<<<1, 256>>>(M, we1, be1, we2, be2, we3, be3, lng, lnb);
    eig_kernel<<<256 * 22, 256>>>(x);
    dense1_kernel<<<dim3(32, 256), 128>>>(w2, b2, w3, b3);
    dense2_kernel<<<dim3(32, 256), 128>>>(w4, b4, w5, b5);
    head_kernel<<<1, 256>>>(w, (float*)d_out);
}

// round 14
// speedup vs baseline: 1.1427x; 1.1427x over previous
#include <cuda_runtime.h>
#include <cuda_bf16.h>
#include <math.h>

// ---------------- scratch (static device globals; no allocation) ----------------
__device__ float g_lbuf[256 * 22 * 4096];   // log-eig planes, layout [n][ch][pos]
__device__ float g_eusum[256 * 22];
__device__ float g_eusq[256 * 22];
__device__ float g_h2sum[256 * 32];
__device__ float g_h2sq[256 * 32];
__device__ float g_cov3[256 * 32];
__device__ float g_em3[10];

#define MAXSWEEPS 10
#define UPAD 68   // U column stride (floats); 16B-aligned

typedef unsigned long long ull;

// ---- packed f32x2 helpers (sm_103a; ptxas only emits FFMA2 via PTX) ----
__device__ __forceinline__ ull f2mul(ull a, ull b) {
    ull d; asm("mul.rn.f32x2 %0, %1, %2;" : "=l"(d) : "l"(a), "l"(b)); return d;
}
__device__ __forceinline__ ull f2fma(ull a, ull b, ull c) {
    ull d; asm("fma.rn.f32x2 %0, %1, %2, %3;" : "=l"(d) : "l"(a), "l"(b), "l"(c)); return d;
}
__device__ __forceinline__ ull f2pack(float lo, float hi) {
    ull d; asm("mov.b64 %0, {%1, %2};" : "=l"(d) : "f"(lo), "f"(hi)); return d;
}
__device__ __forceinline__ float2 f2unpack(ull v) {
    float lo, hi; asm("mov.b64 {%0, %1}, %2;" : "=f"(lo), "=f"(hi) : "l"(v));
    return make_float2(lo, hi);
}

// round-robin pairing: round r in [0,63), pair k in [0,32)
__device__ __forceinline__ void pairpq(int r, int k, int& p, int& q) {
    if (k == 0) { p = 63; q = r; }
    else {
        p = r + k; if (p >= 63) p -= 63;
        q = r - k; if (q < 0)  q += 63;
    }
}

// ---------------- K0: init accumulators + scalar-embedding MLP ----------------
__global__ void init_kernel(const void* __restrict__ Mraw,
                            const float* __restrict__ we1, const float* __restrict__ be1,
                            const float* __restrict__ we2, const float* __restrict__ be2,
                            const float* __restrict__ we3, const float* __restrict__ be3,
                            const float* __restrict__ ln_g, const float* __restrict__ ln_b) {
    const int t = threadIdx.x;  // 256 threads, 1 block
    for (int i = t; i < 256 * 32; i += 256) {
        g_h2sum[i] = 0.f; g_h2sq[i] = 0.f; g_cov3[i] = 0.f;
    }
    __shared__ float md[2];
    __shared__ float em[10], emln[10], em2[100];
    __shared__ float mu_s, isd_s;
    if (t == 0) {
        int mi = *(const int*)Mraw;
        float Mv = (mi > 0 && mi < 100000000) ? (float)mi : __int_as_float(mi);
        md[0] = Mv / 500.0f;
        md[1] = 64.0f / 100.0f;
    }
    __syncthreads();
    if (t < 10) em[t] = md[0] * we1[t] + md[1] * we1[10 + t] + be1[t];
    __syncthreads();
    if (t == 0) {
        float s = 0.f, s2 = 0.f;
        for (int j = 0; j < 10; ++j) { s += em[j]; s2 += em[j] * em[j]; }
        float mu = s * 0.1f;
        float var = fmaxf(s2 * 0.1f - mu * mu, 0.f);
        mu_s = mu;
        isd_s = rsqrtf(var + 1e-3f);   // keras LN: eps inside sqrt
    }
    __syncthreads();
    if (t < 10) emln[t] = (em[t] - mu_s) * isd_s * ln_g[t] + ln_b[t];
    __syncthreads();
    if (t < 100) {
        float a = be2[t];
        for (int j = 0; j < 10; ++j) a += emln[j] * we2[j * 100 + t];
        em2[t] = fmaxf(a, 0.f);
    }
    __syncthreads();
    if (t < 10) {
        float a = be3[t];
        for (int k = 0; k < 100; ++k) a += em2[k] * we3[k * 10 + t];
        g_em3[t] = em[t] + a;
    }
}

// ---------------- K1: shifted one-sided Jacobi (R12 structure, 128-thr CTAs) ------
// U = A + sigma*I (PD), column-major (stride UPAD). 16 quarter-warps each
// handle 2 of the 32 pairs per round, in smem with packed f32x2 math.
// 128-thread CTAs: cheaper barriers + ~10 CTAs/SM to hide the dot-chain.
// lambda_c = ||u_c|| - sigma; L = sum_c (f_c/||u_c||^2) u_c u_c^T.
__global__ __launch_bounds__(128, 10) void eig_kernel(const float* __restrict__ x) {
    __shared__ __align__(16) float U[64 * UPAD];
    __shared__ float nrm[64];
    __shared__ float gsc[64];
    __shared__ float wred[8];
    __shared__ float sig_s, sig2_s;
    __shared__ int conv_s;

    const int t = threadIdx.x;
    const int warp = t >> 5, lane = t & 31;
    const int b = blockIdx.x;      // n*22 + ch
    const float* src = x + (size_t)b * 4096;

    // load plane (coalesced) into U column-major
    #pragma unroll
    for (int it = 0; it < 32; ++it) {
        int id = t + 128 * it;
        int r_ = id >> 6, c_ = id & 63;
        U[c_ * UPAD + r_] = src[id];
    }
    __syncthreads();
    // symmetrize in smem + Frobenius norm^2
    float fn = 0.f;
    #pragma unroll
    for (int it = 0; it < 32; ++it) {
        int id = t + 128 * it;
        int i = id >> 6, j = id & 63;
        if (i < j) {
            float a = 0.5f * (U[i * UPAD + j] + U[j * UPAD + i]);
            U[i * UPAD + j] = a; U[j * UPAD + i] = a;
            fn += 2.f * a * a;
        } else if (i == j) {
            float d = U[i * UPAD + i];
            fn += d * d;
        }
    }
    #pragma unroll
    for (int off = 16; off; off >>= 1) fn += __shfl_xor_sync(0xffffffffu, fn, off);
    if (lane == 0) wred[warp] = fn;
    __syncthreads();
    if (t == 0) {
        float s = wred[0] + wred[1] + wred[2] + wred[3];
        sig2_s = s;
        sig_s = sqrtf(s);
        conv_s = 0;
    }
    __syncthreads();
    const float sigma = sig_s;
    if (t < 64) U[t * UPAD + t] += sigma;   // shift: U = A + sigma*I  (PD)
    __syncthreads();
    // initial column sq-norms (one-time)
    if (t < 64) {
        const float* uc = U + t * UPAD;
        float s = 0.f;
        #pragma unroll 8
        for (int r_ = 0; r_ < 64; ++r_) { float v = uc[r_]; s += v * v; }
        nrm[t] = s;
    }
    __syncthreads();

    const float skipthr = 4e-5f * sig2_s + 1e-30f;
    const float convthr = 4e-4f * sig2_s + 1e-30f;

    const int ql = lane & 7;                   // lane within quarter
    const int qid = (warp << 2) | (lane >> 3); // quarter id 0..15

    for (int sweep = 0; sweep < MAXSWEEPS; ++sweep) {
        float swmax = 0.f;
        for (int r = 0; r < 63; ++r) {
            #pragma unroll
            for (int j = 0; j < 2; ++j) {
                int k = (qid << 1) | j;
                int p, q; pairpq(r, k, p, q);
                ulonglong2* Up = (ulonglong2*)(U + p * UPAD);
                ulonglong2* Uq = (ulonglong2*)(U + q * UPAD);
                ulonglong2 A0 = Up[ql], A1 = Up[ql + 8];
                ulonglong2 B0 = Uq[ql], B1 = Uq[ql + 8];
                ull acc = f2mul(A0.x, B0.x);
                acc = f2fma(A0.y, B0.y, acc);
                acc = f2fma(A1.x, B1.x, acc);
                acc = f2fma(A1.y, B1.y, acc);
                float2 ac = f2unpack(acc);
                float spq = ac.x + ac.y;
                #pragma unroll
                for (int off = 4; off; off >>= 1)
                    spq += __shfl_xor_sync(0xffffffffu, spq, off);
                swmax = fmaxf(swmax, fabsf(spq));
                if (fabsf(spq) > skipthr) {
                    float dpp = nrm[p], dqq = nrm[q];
                    float tau = (dqq - dpp) / (2.f * spq);
                    float tt = copysignf(1.f, tau) / (fabsf(tau) + sqrtf(1.f + tau * tau));
                    float c = rsqrtf(1.f + tt * tt);
                    float s = tt * c;
                    ull c2 = f2pack(c, c), s2 = f2pack(s, s), ns2 = f2pack(-s, -s);
                    ulonglong2 N0, N1, M0, M1;
                    N0.x = f2fma(A0.x, c2, f2mul(B0.x, ns2));
                    N0.y = f2fma(A0.y, c2, f2mul(B0.y, ns2));
                    N1.x = f2fma(A1.x, c2, f2mul(B1.x, ns2));
                    N1.y = f2fma(A1.y, c2, f2mul(B1.y, ns2));
                    M0.x = f2fma(A0.x, s2, f2mul(B0.x, c2));
                    M0.y = f2fma(A0.y, s2, f2mul(B0.y, c2));
                    M1.x = f2fma(A1.x, s2, f2mul(B1.x, c2));
                    M1.y = f2fma(A1.y, s2, f2mul(B1.y, c2));
                    Up[ql] = N0; Up[ql + 8] = N1;
                    Uq[ql] = M0; Uq[ql + 8] = M1;
                    if (ql == 0) {
                        float cc = c * c, ss = s * s, cs2 = 2.f * c * s * spq;
                        nrm[p] = cc * dpp + ss * dqq - cs2;
                        nrm[q] = ss * dpp + cc * dqq + cs2;
                    }
                }
            }
            __syncthreads();
        }
        // merge quarters' swmax, then block-reduce
        swmax = fmaxf(swmax, __shfl_xor_sync(0xffffffffu, swmax, 8));
        swmax = fmaxf(swmax, __shfl_xor_sync(0xffffffffu, swmax, 16));
        if (lane == 0) wred[warp] = swmax;
        __syncthreads();
        if (t == 0) {
            float m = fmaxf(fmaxf(wred[0], wred[1]), fmaxf(wred[2], wred[3]));
            conv_s = (m < convthr) ? 1 : 0;
        }
        __syncthreads();
        if (conv_s) break;
    }

    // exact column norms (double), lambda = ||u|| - sigma, scale g = f/||u||^2
    if (t < 64) {
        const float* uc = U + t * UPAD;
        double s = 0.0;
        #pragma unroll 8
        for (int r_ = 0; r_ < 64; ++r_) { double v = (double)uc[r_]; s += v * v; }
        double rho = sqrt(s);
        float lam = (float)(rho - (double)sigma);
        float f = logf(fmaxf(lam, 1e-4f));
        gsc[t] = (float)((double)f / s);
    }
    __syncthreads();

    // L[i][j] = sum_m gsc[m] * U[m][i] * U[m][j]; thread: row t>>1, 2x16-col chunks
    const int i0 = t >> 1;
    float lsum = 0.f, lsq = 0.f;
    float* dst = g_lbuf + (size_t)b * 4096;
    #pragma unroll
    for (int chunk = 0; chunk < 2; ++chunk) {
        const int j0 = ((t & 1) << 5) + (chunk << 4);
        float acc16[16];
        #pragma unroll
        for (int jj = 0; jj < 16; ++jj) acc16[jj] = 0.f;
        #pragma unroll 4
        for (int m = 0; m < 64; ++m) {
            float a = gsc[m] * U[m * UPAD + i0];
            const float* ur = U + m * UPAD + j0;
            #pragma unroll
            for (int jj = 0; jj < 16; ++jj) acc16[jj] += a * ur[jj];
        }
        #pragma unroll
        for (int jj = 0; jj < 16; ++jj) {
            float v = acc16[jj];
            dst[i0 * 64 + j0 + jj] = v;
            lsum += v; lsq += v * v;
        }
    }
    #pragma unroll
    for (int off = 16; off; off >>= 1) {
        lsum += __shfl_down_sync(0xffffffffu, lsum, off);
        lsq  += __shfl_down_sync(0xffffffffu, lsq, off);
    }
    if (lane == 0) { wred[warp] = lsum; wred[4 + warp] = lsq; }
    __syncthreads();
    if (t == 0) {
        g_eusum[b] = wred[0] + wred[1] + wred[2] + wred[3];
        g_eusq[b]  = wred[4] + wred[5] + wred[6] + wred[7];
    }
}

// ---------------- K2: block-1 STATS ONLY (h2 is recomputed in K3) ----------------
__global__ __launch_bounds__(128) void dense1_kernel(const float* __restrict__ w2, const float* __restrict__ b2,
                                                     const float* __restrict__ w3, const float* __restrict__ b3) {
    const int t = threadIdx.x;
    const int n = blockIdx.y;
    const int pos = blockIdx.x * 128 + t;
    __shared__ float sw2[1024], sw3[1024], sb2[32], sb3[32];
    __shared__ float meanS[22], isdS[22], em3S[10];
    __shared__ float acc1[32], acc2[32];
    for (int i = t; i < 1024; i += 128) { sw2[i] = w2[i]; sw3[i] = w3[i]; }
    if (t < 32) { sb2[t] = b2[t]; sb3[t] = b3[t]; acc1[t] = 0.f; acc2[t] = 0.f; }
    if (t < 22) {
        float mu = g_eusum[n * 22 + t] * (1.f / 4096.f);
        float var = fmaxf(g_eusq[n * 22 + t] * (1.f / 4096.f) - mu * mu, 0.f);
        meanS[t] = mu;
        isdS[t] = 1.f / fmaxf(sqrtf(var), 1e-3f);   // matnorm: clamp OUTSIDE sqrt
    }
    if (t < 10) em3S[t] = g_em3[t];
    __syncthreads();

    float eu[32];
    #pragma unroll
    for (int c = 0; c < 22; ++c) eu[c] = g_lbuf[((size_t)n * 22 + c) * 4096 + pos];
    #pragma unroll
    for (int c = 22; c < 32; ++c) eu[c] = em3S[c - 22];
    float mt[22];
    #pragma unroll
    for (int c = 0; c < 22; ++c) mt[c] = (eu[c] - meanS[c]) * isdS[c];
    float res[32];
    #pragma unroll
    for (int o = 0; o < 32; ++o) {
        float a = sb2[o];
        #pragma unroll
        for (int c = 0; c < 22; ++c) a += mt[c] * sw2[c * 32 + o];
        res[o] = fmaxf(a, 0.f);
    }
    #pragma unroll
    for (int o = 0; o < 32; ++o) {
        float a = sb3[o];
        #pragma unroll
        for (int c = 0; c < 32; ++c) a += res[c] * sw3[c * 32 + o];
        float h = eu[o] + a;
        float s1 = h, s2 = h * h;
        #pragma unroll
        for (int off = 16; off; off >>= 1) {
            s1 += __shfl_down_sync(0xffffffffu, s1, off);
            s2 += __shfl_down_sync(0xffffffffu, s2, off);
        }
        if ((t & 31) == 0) { atomicAdd(&acc1[o], s1); atomicAdd(&acc2[o], s2); }
    }
    __syncthreads();
    if (t < 32) {
        atomicAdd(&g_h2sum[n * 32 + t], acc1[t]);
        atomicAdd(&g_h2sq[n * 32 + t], acc2[t]);
    }
}

// ---------------- K3: recompute h2 + block 2 + cov3 accumulation ----------------
__global__ __launch_bounds__(128) void dense2_kernel(const float* __restrict__ w2, const float* __restrict__ b2,
                                                     const float* __restrict__ w3, const float* __restrict__ b3,
                                                     const float* __restrict__ w4, const float* __restrict__ b4,
                                                     const float* __restrict__ w5, const float* __restrict__ b5) {
    const int t = threadIdx.x;
    const int n = blockIdx.y;
    const int pos = blockIdx.x * 128 + t;
    __shared__ float sw2[1024], sw3[1024], sw4[1024], sw5[1024];
    __shared__ float sb2[32], sb3[32], sb4[32], sb5[32];
    __shared__ float meanE[22], isdE[22], em3S[10];
    __shared__ float meanH[32], isdH[32];
    __shared__ float acc1[32];
    for (int i = t; i < 1024; i += 128) {
        sw2[i] = w2[i]; sw3[i] = w3[i]; sw4[i] = w4[i]; sw5[i] = w5[i];
    }
    if (t < 32) {
        sb2[t] = b2[t]; sb3[t] = b3[t]; sb4[t] = b4[t]; sb5[t] = b5[t];
        acc1[t] = 0.f;
        float mu = g_h2sum[n * 32 + t] * (1.f / 4096.f);
        float var = fmaxf(g_h2sq[n * 32 + t] * (1.f / 4096.f) - mu * mu, 0.f);
        meanH[t] = mu;
        isdH[t] = 1.f / fmaxf(sqrtf(var), 1e-3f);
    }
    if (t < 22) {
        float mu = g_eusum[n * 22 + t] * (1.f / 4096.f);
        float var = fmaxf(g_eusq[n * 22 + t] * (1.f / 4096.f) - mu * mu, 0.f);
        meanE[t] = mu;
        isdE[t] = 1.f / fmaxf(sqrtf(var), 1e-3f);
    }
    if (t < 10) em3S[t] = g_em3[t];
    __syncthreads();

    // recompute h2 (bitwise-identical ops to dense1)
    float eu[32];
    #pragma unroll
    for (int c = 0; c < 22; ++c) eu[c] = g_lbuf[((size_t)n * 22 + c) * 4096 + pos];
    #pragma unroll
    for (int c = 22; c < 32; ++c) eu[c] = em3S[c - 22];
    float mt[22];
    #pragma unroll
    for (int c = 0; c < 22; ++c) mt[c] = (eu[c] - meanE[c]) * isdE[c];
    float res[32];
    #pragma unroll
    for (int o = 0; o < 32; ++o) {
        float a = sb2[o];
        #pragma unroll
        for (int c = 0; c < 22; ++c) a += mt[c] * sw2[c * 32 + o];
        res[o] = fmaxf(a, 0.f);
    }
    float hv[32];
    #pragma unroll
    for (int o = 0; o < 32; ++o) {
        float a = sb3[o];
        #pragma unroll
        for (int c = 0; c < 32; ++c) a += res[c] * sw3[c * 32 + o];
        hv[o] = eu[o] + a;
    }
    // block 2
    float mt2[32];
    #pragma unroll
    for (int c = 0; c < 32; ++c) mt2[c] = (hv[c] - meanH[c]) * isdH[c];
    float res2[32];
    #pragma unroll
    for (int o = 0; o < 32; ++o) {
        float a = sb4[o];
        #pragma unroll
        for (int c = 0; c < 32; ++c) a += mt2[c] * sw4[c * 32 + o];
        res2[o] = fmaxf(a, 0.f);
    }
    #pragma unroll
    for (int o = 0; o < 32; ++o) {
        float a = sb5[o];
        #pragma unroll
        for (int c = 0; c < 32; ++c) a += res2[c] * sw5[c * 32 + o];
        float h = hv[o] + a;
        float s1 = h;
        #pragma unroll
        for (int off = 16; off; off >>= 1) s1 += __shfl_down_sync(0xffffffffu, s1, off);
        if ((t & 31) == 0) atomicAdd(&acc1[o], s1);
    }
    __syncthreads();
    if (t < 32) atomicAdd(&g_cov3[n * 32 + t], acc1[t]);
}

// ---------------- K4: head (cov3 @ w -> softmax) ----------------
__global__ void head_kernel(const float* __restrict__ w, float* __restrict__ out) {
    const int n = threadIdx.x;  // 256 threads
    float c[32];
    #pragma unroll
    for (int ch = 0; ch < 32; ++ch) c[ch] = g_cov3[n * 32 + ch] * (1.f / 4096.f);
    float lg[7];
    #pragma unroll
    for (int cls = 0; cls < 7; ++cls) {
        float a = 0.f;
        #pragma unroll
        for (int ch = 0; ch < 32; ++ch) a += c[ch] * w[ch * 7 + cls];
        lg[cls] = a;
    }
    float mx = lg[0];
    #pragma unroll
    for (int cls = 1; cls < 7; ++cls) mx = fmaxf(mx, lg[cls]);
    float sum = 0.f;
    #pragma unroll
    for (int cls = 0; cls < 7; ++cls) { lg[cls] = expf(lg[cls] - mx); sum += lg[cls]; }
    float inv = 1.f / sum;
    #pragma unroll
    for (int cls = 0; cls < 7; ++cls) out[n * 7 + cls] = lg[cls] * inv;
}

// ---------------- launch ----------------
extern "C" void kernel_launch(void* const* d_in, const int* in_sizes, int n_in,
                              void* d_out, int out_size) {
    const float* x   = (const float*)d_in[0];
    const void*  M   = d_in[1];
    const float* w   = (const float*)d_in[2];
    const float* w2  = (const float*)d_in[3];
    const float* b2  = (const float*)d_in[4];
    const float* w3  = (const float*)d_in[5];
    const float* b3  = (const float*)d_in[6];
    const float* w4  = (const float*)d_in[7];
    const float* b4  = (const float*)d_in[8];
    const float* w5  = (const float*)d_in[9];
    const float* b5  = (const float*)d_in[10];
    const float* we1 = (const float*)d_in[11];
    const float* be1 = (const float*)d_in[12];
    const float* we2 = (const float*)d_in[13];
    const float* be2 = (const float*)d_in[14];
    const float* we3 = (const float*)d_in[15];
    const float* be3 = (const float*)d_in[16];
    const float* lng = (const float*)d_in[17];
    const float* lnb = (const float*)d_in[18];

    init_kernel<<<1, 256>>>(M, we1, be1, we2, be2, we3, be3, lng, lnb);
    eig_kernel<<<256 * 22, 128>>>(x);
    dense1_kernel<<<dim3(32, 256), 128>>>(w2, b2, w3, b3);
    dense2_kernel<<<dim3(32, 256), 128>>>(w2, b2, w3, b3, w4, b4, w5, b5);
    head_kernel<<<1, 256>>>(w, (float*)d_out);
}

// round 15
// speedup vs baseline: 1.1945x; 1.0453x over previous
#include <cuda_runtime.h>
#include <cuda_bf16.h>
#include <math.h>

// ---------------- scratch (static device globals; no allocation) ----------------
__device__ float g_lbuf[256 * 22 * 4096];   // log-eig planes, layout [n][ch][pos]
__device__ float g_h2[256 * 32 * 4096];     // h2, layout [n][ch][pos]
__device__ float g_eusum[256 * 22];
__device__ float g_eusq[256 * 22];
__device__ float g_h2sum[256 * 32];
__device__ float g_h2sq[256 * 32];
__device__ float g_cov3[256 * 32];
__device__ float g_em3[10];

#define MAXSWEEPS 10
#define UPAD 68   // U column stride (floats); 16B-aligned

typedef unsigned long long ull;

// ---- packed f32x2 helpers (sm_103a; ptxas only emits FFMA2 via PTX) ----
__device__ __forceinline__ ull f2mul(ull a, ull b) {
    ull d; asm("mul.rn.f32x2 %0, %1, %2;" : "=l"(d) : "l"(a), "l"(b)); return d;
}
__device__ __forceinline__ ull f2fma(ull a, ull b, ull c) {
    ull d; asm("fma.rn.f32x2 %0, %1, %2, %3;" : "=l"(d) : "l"(a), "l"(b), "l"(c)); return d;
}
__device__ __forceinline__ ull f2pack(float lo, float hi) {
    ull d; asm("mov.b64 %0, {%1, %2};" : "=l"(d) : "f"(lo), "f"(hi)); return d;
}
__device__ __forceinline__ float2 f2unpack(ull v) {
    float lo, hi; asm("mov.b64 {%0, %1}, %2;" : "=f"(lo), "=f"(hi) : "l"(v));
    return make_float2(lo, hi);
}

// round-robin pairing: round r in [0,63), pair k in [0,32)
__device__ __forceinline__ void pairpq(int r, int k, int& p, int& q) {
    if (k == 0) { p = 63; q = r; }
    else {
        p = r + k; if (p >= 63) p -= 63;
        q = r - k; if (q < 0)  q += 63;
    }
}

// ---------------- K0: init accumulators + scalar-embedding MLP ----------------
__global__ void init_kernel(const void* __restrict__ Mraw,
                            const float* __restrict__ we1, const float* __restrict__ be1,
                            const float* __restrict__ we2, const float* __restrict__ be2,
                            const float* __restrict__ we3, const float* __restrict__ be3,
                            const float* __restrict__ ln_g, const float* __restrict__ ln_b) {
    const int t = threadIdx.x;  // 256 threads, 1 block
    for (int i = t; i < 256 * 32; i += 256) {
        g_h2sum[i] = 0.f; g_h2sq[i] = 0.f; g_cov3[i] = 0.f;
    }
    __shared__ float md[2];
    __shared__ float em[10], emln[10], em2[100];
    __shared__ float mu_s, isd_s;
    if (t == 0) {
        int mi = *(const int*)Mraw;
        float Mv = (mi > 0 && mi < 100000000) ? (float)mi : __int_as_float(mi);
        md[0] = Mv / 500.0f;
        md[1] = 64.0f / 100.0f;
    }
    __syncthreads();
    if (t < 10) em[t] = md[0] * we1[t] + md[1] * we1[10 + t] + be1[t];
    __syncthreads();
    if (t == 0) {
        float s = 0.f, s2 = 0.f;
        for (int j = 0; j < 10; ++j) { s += em[j]; s2 += em[j] * em[j]; }
        float mu = s * 0.1f;
        float var = fmaxf(s2 * 0.1f - mu * mu, 0.f);
        mu_s = mu;
        isd_s = rsqrtf(var + 1e-3f);   // keras LN: eps inside sqrt
    }
    __syncthreads();
    if (t < 10) emln[t] = (em[t] - mu_s) * isd_s * ln_g[t] + ln_b[t];
    __syncthreads();
    if (t < 100) {
        float a = be2[t];
        for (int j = 0; j < 10; ++j) a += emln[j] * we2[j * 100 + t];
        em2[t] = fmaxf(a, 0.f);
    }
    __syncthreads();
    if (t < 10) {
        float a = be3[t];
        for (int k = 0; k < 100; ++k) a += em2[k] * we3[k * 10 + t];
        g_em3[t] = em[t] + a;
    }
}

// ---------------- K1: shifted one-sided Jacobi (128-thr CTAs, quarter-warp pairs) --
// U = A + sigma*I (PD), column-major (stride UPAD). 16 quarter-warps each
// handle 2 of the 32 pairs per round, in smem with packed f32x2 math.
// lambda_c = ||u_c|| - sigma; L = sum_c (f_c/||u_c||^2) u_c u_c^T.
__global__ __launch_bounds__(128, 10) void eig_kernel(const float* __restrict__ x) {
    __shared__ __align__(16) float U[64 * UPAD];
    __shared__ float nrm[64];
    __shared__ float gsc[64];
    __shared__ float wred[8];
    __shared__ float sig_s, sig2_s;
    __shared__ int conv_s;

    const int t = threadIdx.x;
    const int warp = t >> 5, lane = t & 31;
    const int b = blockIdx.x;      // n*22 + ch
    const float* src = x + (size_t)b * 4096;

    // load plane (coalesced) into U column-major
    #pragma unroll
    for (int it = 0; it < 32; ++it) {
        int id = t + 128 * it;
        int r_ = id >> 6, c_ = id & 63;
        U[c_ * UPAD + r_] = src[id];
    }
    __syncthreads();
    // symmetrize in smem + Frobenius norm^2
    float fn = 0.f;
    #pragma unroll
    for (int it = 0; it < 32; ++it) {
        int id = t + 128 * it;
        int i = id >> 6, j = id & 63;
        if (i < j) {
            float a = 0.5f * (U[i * UPAD + j] + U[j * UPAD + i]);
            U[i * UPAD + j] = a; U[j * UPAD + i] = a;
            fn += 2.f * a * a;
        } else if (i == j) {
            float d = U[i * UPAD + i];
            fn += d * d;
        }
    }
    #pragma unroll
    for (int off = 16; off; off >>= 1) fn += __shfl_xor_sync(0xffffffffu, fn, off);
    if (lane == 0) wred[warp] = fn;
    __syncthreads();
    if (t == 0) {
        float s = wred[0] + wred[1] + wred[2] + wred[3];
        sig2_s = s;
        sig_s = sqrtf(s);
        conv_s = 0;
    }
    __syncthreads();
    const float sigma = sig_s;
    if (t < 64) U[t * UPAD + t] += sigma;   // shift: U = A + sigma*I  (PD)
    __syncthreads();
    // initial column sq-norms (one-time)
    if (t < 64) {
        const float* uc = U + t * UPAD;
        float s = 0.f;
        #pragma unroll 8
        for (int r_ = 0; r_ < 64; ++r_) { float v = uc[r_]; s += v * v; }
        nrm[t] = s;
    }
    __syncthreads();

    const float skipthr = 4e-5f * sig2_s + 1e-30f;
    const float convthr = 4e-4f * sig2_s + 1e-30f;

    const int ql = lane & 7;                   // lane within quarter
    const int qid = (warp << 2) | (lane >> 3); // quarter id 0..15

    for (int sweep = 0; sweep < MAXSWEEPS; ++sweep) {
        float swmax = 0.f;
        for (int r = 0; r < 63; ++r) {
            #pragma unroll
            for (int j = 0; j < 2; ++j) {
                int k = (qid << 1) | j;
                int p, q; pairpq(r, k, p, q);
                ulonglong2* Up = (ulonglong2*)(U + p * UPAD);
                ulonglong2* Uq = (ulonglong2*)(U + q * UPAD);
                ulonglong2 A0 = Up[ql], A1 = Up[ql + 8];
                ulonglong2 B0 = Uq[ql], B1 = Uq[ql + 8];
                ull acc = f2mul(A0.x, B0.x);
                acc = f2fma(A0.y, B0.y, acc);
                acc = f2fma(A1.x, B1.x, acc);
                acc = f2fma(A1.y, B1.y, acc);
                float2 ac = f2unpack(acc);
                float spq = ac.x + ac.y;
                #pragma unroll
                for (int off = 4; off; off >>= 1)
                    spq += __shfl_xor_sync(0xffffffffu, spq, off);
                swmax = fmaxf(swmax, fabsf(spq));
                if (fabsf(spq) > skipthr) {
                    float dpp = nrm[p], dqq = nrm[q];
                    float tau = (dqq - dpp) / (2.f * spq);
                    float tt = copysignf(1.f, tau) / (fabsf(tau) + sqrtf(1.f + tau * tau));
                    float c = rsqrtf(1.f + tt * tt);
                    float s = tt * c;
                    ull c2 = f2pack(c, c), s2 = f2pack(s, s), ns2 = f2pack(-s, -s);
                    ulonglong2 N0, N1, M0, M1;
                    N0.x = f2fma(A0.x, c2, f2mul(B0.x, ns2));
                    N0.y = f2fma(A0.y, c2, f2mul(B0.y, ns2));
                    N1.x = f2fma(A1.x, c2, f2mul(B1.x, ns2));
                    N1.y = f2fma(A1.y, c2, f2mul(B1.y, ns2));
                    M0.x = f2fma(A0.x, s2, f2mul(B0.x, c2));
                    M0.y = f2fma(A0.y, s2, f2mul(B0.y, c2));
                    M1.x = f2fma(A1.x, s2, f2mul(B1.x, c2));
                    M1.y = f2fma(A1.y, s2, f2mul(B1.y, c2));
                    Up[ql] = N0; Up[ql + 8] = N1;
                    Uq[ql] = M0; Uq[ql + 8] = M1;
                    if (ql == 0) {
                        float cc = c * c, ss = s * s, cs2 = 2.f * c * s * spq;
                        nrm[p] = cc * dpp + ss * dqq - cs2;
                        nrm[q] = ss * dpp + cc * dqq + cs2;
                    }
                }
            }
            __syncthreads();
        }
        // merge quarters' swmax, then block-reduce
        swmax = fmaxf(swmax, __shfl_xor_sync(0xffffffffu, swmax, 8));
        swmax = fmaxf(swmax, __shfl_xor_sync(0xffffffffu, swmax, 16));
        if (lane == 0) wred[warp] = swmax;
        __syncthreads();
        if (t == 0) {
            float m = fmaxf(fmaxf(wred[0], wred[1]), fmaxf(wred[2], wred[3]));
            conv_s = (m < convthr) ? 1 : 0;
        }
        __syncthreads();
        if (conv_s) break;
    }

    // exact column norms (double), lambda = ||u|| - sigma, scale g = f/||u||^2
    if (t < 64) {
        const float* uc = U + t * UPAD;
        double s = 0.0;
        #pragma unroll 8
        for (int r_ = 0; r_ < 64; ++r_) { double v = (double)uc[r_]; s += v * v; }
        double rho = sqrt(s);
        float lam = (float)(rho - (double)sigma);
        float f = logf(fmaxf(lam, 1e-4f));
        gsc[t] = (float)((double)f / s);
    }
    __syncthreads();

    // L[i][j] = sum_m gsc[m] * U[m][i] * U[m][j]; thread: row t>>1, 2x16-col chunks
    const int i0 = t >> 1;
    float lsum = 0.f, lsq = 0.f;
    float* dst = g_lbuf + (size_t)b * 4096;
    #pragma unroll
    for (int chunk = 0; chunk < 2; ++chunk) {
        const int j0 = ((t & 1) << 5) + (chunk << 4);
        float acc16[16];
        #pragma unroll
        for (int jj = 0; jj < 16; ++jj) acc16[jj] = 0.f;
        #pragma unroll 4
        for (int m = 0; m < 64; ++m) {
            float a = gsc[m] * U[m * UPAD + i0];
            const float* ur = U + m * UPAD + j0;
            #pragma unroll
            for (int jj = 0; jj < 16; ++jj) acc16[jj] += a * ur[jj];
        }
        #pragma unroll
        for (int jj = 0; jj < 16; ++jj) {
            float v = acc16[jj];
            dst[i0 * 64 + j0 + jj] = v;
            lsum += v; lsq += v * v;
        }
    }
    #pragma unroll
    for (int off = 16; off; off >>= 1) {
        lsum += __shfl_down_sync(0xffffffffu, lsum, off);
        lsq  += __shfl_down_sync(0xffffffffu, lsq, off);
    }
    if (lane == 0) { wred[warp] = lsum; wred[4 + warp] = lsq; }
    __syncthreads();
    if (t == 0) {
        g_eusum[b] = wred[0] + wred[1] + wred[2] + wred[3];
        g_eusq[b]  = wred[4] + wred[5] + wred[6] + wred[7];
    }
}

// ---------------- K2: block 1  (matnorm(eu) @ w2 -> relu -> @w3 + eu) ----------------
__global__ __launch_bounds__(128) void dense1_kernel(const float* __restrict__ w2, const float* __restrict__ b2,
                                                     const float* __restrict__ w3, const float* __restrict__ b3) {
    const int t = threadIdx.x;
    const int n = blockIdx.y;
    const int pos = blockIdx.x * 128 + t;
    __shared__ float sw2[1024], sw3[1024], sb2[32], sb3[32];
    __shared__ float meanS[22], isdS[22], em3S[10];
    __shared__ float acc1[32], acc2[32];
    for (int i = t; i < 1024; i += 128) { sw2[i] = w2[i]; sw3[i] = w3[i]; }
    if (t < 32) { sb2[t] = b2[t]; sb3[t] = b3[t]; acc1[t] = 0.f; acc2[t] = 0.f; }
    if (t < 22) {
        float mu = g_eusum[n * 22 + t] * (1.f / 4096.f);
        float var = fmaxf(g_eusq[n * 22 + t] * (1.f / 4096.f) - mu * mu, 0.f);
        meanS[t] = mu;
        isdS[t] = 1.f / fmaxf(sqrtf(var), 1e-3f);   // matnorm: clamp OUTSIDE sqrt
    }
    if (t < 10) em3S[t] = g_em3[t];
    __syncthreads();

    float eu[32];
    #pragma unroll
    for (int c = 0; c < 22; ++c) eu[c] = g_lbuf[((size_t)n * 22 + c) * 4096 + pos];
    #pragma unroll
    for (int c = 22; c < 32; ++c) eu[c] = em3S[c - 22];
    float mt[22];
    #pragma unroll
    for (int c = 0; c < 22; ++c) mt[c] = (eu[c] - meanS[c]) * isdS[c];
    // matnorm of the constant embedding channels is exactly 0 (std clamped), so skip c>=22
    float res[32];
    #pragma unroll
    for (int o = 0; o < 32; ++o) {
        float a = sb2[o];
        #pragma unroll
        for (int c = 0; c < 22; ++c) a += mt[c] * sw2[c * 32 + o];
        res[o] = fmaxf(a, 0.f);
    }
    #pragma unroll
    for (int o = 0; o < 32; ++o) {
        float a = sb3[o];
        #pragma unroll
        for (int c = 0; c < 32; ++c) a += res[c] * sw3[c * 32 + o];
        float h = eu[o] + a;
        g_h2[((size_t)n * 32 + o) * 4096 + pos] = h;
        float s1 = h, s2 = h * h;
        #pragma unroll
        for (int off = 16; off; off >>= 1) {
            s1 += __shfl_down_sync(0xffffffffu, s1, off);
            s2 += __shfl_down_sync(0xffffffffu, s2, off);
        }
        if ((t & 31) == 0) { atomicAdd(&acc1[o], s1); atomicAdd(&acc2[o], s2); }
    }
    __syncthreads();
    if (t < 32) {
        atomicAdd(&g_h2sum[n * 32 + t], acc1[t]);
        atomicAdd(&g_h2sq[n * 32 + t], acc2[t]);
    }
}

// ---------------- K3: block 2  (matnorm(h2) @ w4 -> relu -> @w5 + h2, mean) ----------------
__global__ __launch_bounds__(128) void dense2_kernel(const float* __restrict__ w4, const float* __restrict__ b4,
                                                     const float* __restrict__ w5, const float* __restrict__ b5) {
    const int t = threadIdx.x;
    const int n = blockIdx.y;
    const int pos = blockIdx.x * 128 + t;
    __shared__ float sw4[1024], sw5[1024], sb4[32], sb5[32];
    __shared__ float meanS[32], isdS[32];
    __shared__ float acc1[32];
    for (int i = t; i < 1024; i += 128) { sw4[i] = w4[i]; sw5[i] = w5[i]; }
    if (t < 32) {
        sb4[t] = b4[t]; sb5[t] = b5[t]; acc1[t] = 0.f;
        float mu = g_h2sum[n * 32 + t] * (1.f / 4096.f);
        float var = fmaxf(g_h2sq[n * 32 + t] * (1.f / 4096.f) - mu * mu, 0.f);
        meanS[t] = mu;
        isdS[t] = 1.f / fmaxf(sqrtf(var), 1e-3f);
    }
    __syncthreads();

    float hv[32];
    #pragma unroll
    for (int c = 0; c < 32; ++c) hv[c] = g_h2[((size_t)n * 32 + c) * 4096 + pos];
    float mt[32];
    #pragma unroll
    for (int c = 0; c < 32; ++c) mt[c] = (hv[c] - meanS[c]) * isdS[c];
    float res[32];
    #pragma unroll
    for (int o = 0; o < 32; ++o) {
        float a = sb4[o];
        #pragma unroll
        for (int c = 0; c < 32; ++c) a += mt[c] * sw4[c * 32 + o];
        res[o] = fmaxf(a, 0.f);
    }
    #pragma unroll
    for (int o = 0; o < 32; ++o) {
        float a = sb5[o];
        #pragma unroll
        for (int c = 0; c < 32; ++c) a += res[c] * sw5[c * 32 + o];
        float h = hv[o] + a;
        float s1 = h;
        #pragma unroll
        for (int off = 16; off; off >>= 1) s1 += __shfl_down_sync(0xffffffffu, s1, off);
        if ((t & 31) == 0) atomicAdd(&acc1[o], s1);
    }
    __syncthreads();
    if (t < 32) atomicAdd(&g_cov3[n * 32 + t], acc1[t]);
}

// ---------------- K4: head (cov3 @ w -> softmax) ----------------
__global__ void head_kernel(const float* __restrict__ w, float* __restrict__ out) {
    const int n = threadIdx.x;  // 256 threads
    float c[32];
    #pragma unroll
    for (int ch = 0; ch < 32; ++ch) c[ch] = g_cov3[n * 32 + ch] * (1.f / 4096.f);
    float lg[7];
    #pragma unroll
    for (int cls = 0; cls < 7; ++cls) {
        float a = 0.f;
        #pragma unroll
        for (int ch = 0; ch < 32; ++ch) a += c[ch] * w[ch * 7 + cls];
        lg[cls] = a;
    }
    float mx = lg[0];
    #pragma unroll
    for (int cls = 1; cls < 7; ++cls) mx = fmaxf(mx, lg[cls]);
    float sum = 0.f;
    #pragma unroll
    for (int cls = 0; cls < 7; ++cls) { lg[cls] = expf(lg[cls] - mx); sum += lg[cls]; }
    float inv = 1.f / sum;
    #pragma unroll
    for (int cls = 0; cls < 7; ++cls) out[n * 7 + cls] = lg[cls] * inv;
}

// ---------------- launch ----------------
extern "C" void kernel_launch(void* const* d_in, const int* in_sizes, int n_in,
                              void* d_out, int out_size) {
    const float* x   = (const float*)d_in[0];
    const void*  M   = d_in[1];
    const float* w   = (const float*)d_in[2];
    const float* w2  = (const float*)d_in[3];
    const float* b2  = (const float*)d_in[4];
    const float* w3  = (const float*)d_in[5];
    const float* b3  = (const float*)d_in[6];
    const float* w4  = (const float*)d_in[7];
    const float* b4  = (const float*)d_in[8];
    const float* w5  = (const float*)d_in[9];
    const float* b5  = (const float*)d_in[10];
    const float* we1 = (const float*)d_in[11];
    const float* be1 = (const float*)d_in[12];
    const float* we2 = (const float*)d_in[13];
    const float* be2 = (const float*)d_in[14];
    const float* we3 = (const float*)d_in[15];
    const float* be3 = (const float*)d_in[16];
    const float* lng = (const float*)d_in[17];
    const float* lnb = (const float*)d_in[18];

    init_kernel<<<1, 256>>>(M, we1, be1, we2, be2, we3, be3, lng, lnb);
    eig_kernel<<<256 * 22, 128>>>(x);
    dense1_kernel<<<dim3(32, 256), 128>>>(w2, b2, w3, b3);
    dense2_kernel<<<dim3(32, 256), 128>>>(w4, b4, w5, b5);
    head_kernel<<<1, 256>>>(w, (float*)d_out);
}

// round 16
// speedup vs baseline: 1.3394x; 1.1214x over previous
#include <cuda_runtime.h>
#include <cuda_bf16.h>
#include <math.h>

// ---------------- scratch (static device globals; no allocation) ----------------
__device__ float g_lbuf[256 * 22 * 4096];   // log-eig planes, layout [n][ch][pos]
__device__ float g_h2[256 * 32 * 4096];     // h2, layout [n][ch][pos]
__device__ float g_eusum[256 * 22];
__device__ float g_eusq[256 * 22];
__device__ float g_h2sum[256 * 32];
__device__ float g_h2sq[256 * 32];
__device__ float g_cov3[256 * 32];
__device__ float g_em3[10];

#define MAXSWEEPS 10
#define UPAD 68   // U column stride (floats); 16B-aligned

typedef unsigned long long ull;

// ---- packed f32x2 helpers (sm_103a; ptxas only emits FFMA2 via PTX) ----
__device__ __forceinline__ ull f2mul(ull a, ull b) {
    ull d; asm("mul.rn.f32x2 %0, %1, %2;" : "=l"(d) : "l"(a), "l"(b)); return d;
}
__device__ __forceinline__ ull f2fma(ull a, ull b, ull c) {
    ull d; asm("fma.rn.f32x2 %0, %1, %2, %3;" : "=l"(d) : "l"(a), "l"(b), "l"(c)); return d;
}
__device__ __forceinline__ ull f2pack(float lo, float hi) {
    ull d; asm("mov.b64 %0, {%1, %2};" : "=l"(d) : "f"(lo), "f"(hi)); return d;
}
__device__ __forceinline__ float2 f2unpack(ull v) {
    float lo, hi; asm("mov.b64 {%0, %1}, %2;" : "=f"(lo), "=f"(hi) : "l"(v));
    return make_float2(lo, hi);
}

// round-robin pairing: round r in [0,63), pair k in [0,32)
__device__ __forceinline__ void pairpq(int r, int k, int& p, int& q) {
    if (k == 0) { p = 63; q = r; }
    else {
        p = r + k; if (p >= 63) p -= 63;
        q = r - k; if (q < 0)  q += 63;
    }
}

// ---------------- K0: init accumulators + scalar-embedding MLP ----------------
__global__ void init_kernel(const void* __restrict__ Mraw,
                            const float* __restrict__ we1, const float* __restrict__ be1,
                            const float* __restrict__ we2, const float* __restrict__ be2,
                            const float* __restrict__ we3, const float* __restrict__ be3,
                            const float* __restrict__ ln_g, const float* __restrict__ ln_b) {
    const int t = threadIdx.x;  // 256 threads, 1 block
    for (int i = t; i < 256 * 32; i += 256) {
        g_h2sum[i] = 0.f; g_h2sq[i] = 0.f; g_cov3[i] = 0.f;
    }
    __shared__ float md[2];
    __shared__ float em[10], emln[10], em2[100];
    __shared__ float mu_s, isd_s;
    if (t == 0) {
        int mi = *(const int*)Mraw;
        float Mv = (mi > 0 && mi < 100000000) ? (float)mi : __int_as_float(mi);
        md[0] = Mv / 500.0f;
        md[1] = 64.0f / 100.0f;
    }
    __syncthreads();
    if (t < 10) em[t] = md[0] * we1[t] + md[1] * we1[10 + t] + be1[t];
    __syncthreads();
    if (t == 0) {
        float s = 0.f, s2 = 0.f;
        for (int j = 0; j < 10; ++j) { s += em[j]; s2 += em[j] * em[j]; }
        float mu = s * 0.1f;
        float var = fmaxf(s2 * 0.1f - mu * mu, 0.f);
        mu_s = mu;
        isd_s = rsqrtf(var + 1e-3f);   // keras LN: eps inside sqrt
    }
    __syncthreads();
    if (t < 10) emln[t] = (em[t] - mu_s) * isd_s * ln_g[t] + ln_b[t];
    __syncthreads();
    if (t < 100) {
        float a = be2[t];
        for (int j = 0; j < 10; ++j) a += emln[j] * we2[j * 100 + t];
        em2[t] = fmaxf(a, 0.f);
    }
    __syncthreads();
    if (t < 10) {
        float a = be3[t];
        for (int k = 0; k < 100; ++k) a += em2[k] * we3[k * 10 + t];
        g_em3[t] = em[t] + a;
    }
}

// ---------------- K1: shifted one-sided Jacobi (128-thr CTAs, quarter-warp pairs) --
// U = A + sigma*I (PD), column-major (stride UPAD). 16 quarter-warps each
// handle 2 of the 32 pairs per round, in smem with packed f32x2 math.
// lambda_c = ||u_c|| - sigma; L = sum_c (f_c/||u_c||^2) u_c u_c^T.
__global__ __launch_bounds__(128, 10) void eig_kernel(const float* __restrict__ x) {
    __shared__ __align__(16) float U[64 * UPAD];
    __shared__ float nrm[64];
    __shared__ float gsc[64];
    __shared__ float wred[8];
    __shared__ float sig_s, sig2_s;
    __shared__ int conv_s;

    const int t = threadIdx.x;
    const int warp = t >> 5, lane = t & 31;
    const int b = blockIdx.x;      // n*22 + ch
    const float* src = x + (size_t)b * 4096;

    // load plane (coalesced) into U column-major
    #pragma unroll
    for (int it = 0; it < 32; ++it) {
        int id = t + 128 * it;
        int r_ = id >> 6, c_ = id & 63;
        U[c_ * UPAD + r_] = src[id];
    }
    __syncthreads();
    // symmetrize in smem + Frobenius norm^2
    float fn = 0.f;
    #pragma unroll
    for (int it = 0; it < 32; ++it) {
        int id = t + 128 * it;
        int i = id >> 6, j = id & 63;
        if (i < j) {
            float a = 0.5f * (U[i * UPAD + j] + U[j * UPAD + i]);
            U[i * UPAD + j] = a; U[j * UPAD + i] = a;
            fn += 2.f * a * a;
        } else if (i == j) {
            float d = U[i * UPAD + i];
            fn += d * d;
        }
    }
    #pragma unroll
    for (int off = 16; off; off >>= 1) fn += __shfl_xor_sync(0xffffffffu, fn, off);
    if (lane == 0) wred[warp] = fn;
    __syncthreads();
    if (t == 0) {
        float s = wred[0] + wred[1] + wred[2] + wred[3];
        sig2_s = s;
        sig_s = sqrtf(s);
        conv_s = 0;
    }
    __syncthreads();
    const float sigma = sig_s;
    if (t < 64) U[t * UPAD + t] += sigma;   // shift: U = A + sigma*I  (PD)
    __syncthreads();
    // initial column sq-norms (one-time)
    if (t < 64) {
        const float* uc = U + t * UPAD;
        float s = 0.f;
        #pragma unroll 8
        for (int r_ = 0; r_ < 64; ++r_) { float v = uc[r_]; s += v * v; }
        nrm[t] = s;
    }
    __syncthreads();

    const float skipthr = 1e-4f * sig2_s + 1e-30f;
    const float convthr = 2e-3f * sig2_s + 1e-30f;

    const int ql = lane & 7;                   // lane within quarter
    const int qid = (warp << 2) | (lane >> 3); // quarter id 0..15

    for (int sweep = 0; sweep < MAXSWEEPS; ++sweep) {
        float swmax = 0.f;
        for (int r = 0; r < 63; ++r) {
            #pragma unroll
            for (int j = 0; j < 2; ++j) {
                int k = (qid << 1) | j;
                int p, q; pairpq(r, k, p, q);
                ulonglong2* Up = (ulonglong2*)(U + p * UPAD);
                ulonglong2* Uq = (ulonglong2*)(U + q * UPAD);
                ulonglong2 A0 = Up[ql], A1 = Up[ql + 8];
                ulonglong2 B0 = Uq[ql], B1 = Uq[ql + 8];
                ull acc = f2mul(A0.x, B0.x);
                acc = f2fma(A0.y, B0.y, acc);
                acc = f2fma(A1.x, B1.x, acc);
                acc = f2fma(A1.y, B1.y, acc);
                float2 ac = f2unpack(acc);
                float spq = ac.x + ac.y;
                #pragma unroll
                for (int off = 4; off; off >>= 1)
                    spq += __shfl_xor_sync(0xffffffffu, spq, off);
                swmax = fmaxf(swmax, fabsf(spq));
                if (fabsf(spq) > skipthr) {
                    float dpp = nrm[p], dqq = nrm[q];
                    float tau = (dqq - dpp) / (2.f * spq);
                    float tt = copysignf(1.f, tau) / (fabsf(tau) + sqrtf(1.f + tau * tau));
                    float c = rsqrtf(1.f + tt * tt);
                    float s = tt * c;
                    ull c2 = f2pack(c, c), s2 = f2pack(s, s), ns2 = f2pack(-s, -s);
                    ulonglong2 N0, N1, M0, M1;
                    N0.x = f2fma(A0.x, c2, f2mul(B0.x, ns2));
                    N0.y = f2fma(A0.y, c2, f2mul(B0.y, ns2));
                    N1.x = f2fma(A1.x, c2, f2mul(B1.x, ns2));
                    N1.y = f2fma(A1.y, c2, f2mul(B1.y, ns2));
                    M0.x = f2fma(A0.x, s2, f2mul(B0.x, c2));
                    M0.y = f2fma(A0.y, s2, f2mul(B0.y, c2));
                    M1.x = f2fma(A1.x, s2, f2mul(B1.x, c2));
                    M1.y = f2fma(A1.y, s2, f2mul(B1.y, c2));
                    Up[ql] = N0; Up[ql + 8] = N1;
                    Uq[ql] = M0; Uq[ql + 8] = M1;
                    if (ql == 0) {
                        float cc = c * c, ss = s * s, cs2 = 2.f * c * s * spq;
                        nrm[p] = cc * dpp + ss * dqq - cs2;
                        nrm[q] = ss * dpp + cc * dqq + cs2;
                    }
                }
            }
            __syncthreads();
        }
        // merge quarters' swmax, then block-reduce
        swmax = fmaxf(swmax, __shfl_xor_sync(0xffffffffu, swmax, 8));
        swmax = fmaxf(swmax, __shfl_xor_sync(0xffffffffu, swmax, 16));
        if (lane == 0) wred[warp] = swmax;
        __syncthreads();
        if (t == 0) {
            float m = fmaxf(fmaxf(wred[0], wred[1]), fmaxf(wred[2], wred[3]));
            conv_s = (m < convthr) ? 1 : 0;
        }
        __syncthreads();
        if (conv_s) break;
    }

    // exact column norms (double), lambda = ||u|| - sigma, scale g = f/||u||^2
    if (t < 64) {
        const float* uc = U + t * UPAD;
        double s = 0.0;
        #pragma unroll 8
        for (int r_ = 0; r_ < 64; ++r_) { double v = (double)uc[r_]; s += v * v; }
        double rho = sqrt(s);
        float lam = (float)(rho - (double)sigma);
        float f = logf(fmaxf(lam, 1e-4f));
        gsc[t] = (float)((double)f / s);
    }
    __syncthreads();

    // L[i][j] = sum_m gsc[m] * U[m][i] * U[m][j]; thread: row t>>1, 2x16-col chunks
    const int i0 = t >> 1;
    float lsum = 0.f, lsq = 0.f;
    float* dst = g_lbuf + (size_t)b * 4096;
    #pragma unroll
    for (int chunk = 0; chunk < 2; ++chunk) {
        const int j0 = ((t & 1) << 5) + (chunk << 4);
        float acc16[16];
        #pragma unroll
        for (int jj = 0; jj < 16; ++jj) acc16[jj] = 0.f;
        #pragma unroll 4
        for (int m = 0; m < 64; ++m) {
            float a = gsc[m] * U[m * UPAD + i0];
            const float* ur = U + m * UPAD + j0;
            #pragma unroll
            for (int jj = 0; jj < 16; ++jj) acc16[jj] += a * ur[jj];
        }
        #pragma unroll
        for (int jj = 0; jj < 16; ++jj) {
            float v = acc16[jj];
            dst[i0 * 64 + j0 + jj] = v;
            lsum += v; lsq += v * v;
        }
    }
    #pragma unroll
    for (int off = 16; off; off >>= 1) {
        lsum += __shfl_down_sync(0xffffffffu, lsum, off);
        lsq  += __shfl_down_sync(0xffffffffu, lsq, off);
    }
    if (lane == 0) { wred[warp] = lsum; wred[4 + warp] = lsq; }
    __syncthreads();
    if (t == 0) {
        g_eusum[b] = wred[0] + wred[1] + wred[2] + wred[3];
        g_eusq[b]  = wred[4] + wred[5] + wred[6] + wred[7];
    }
}

// ---------------- K2: block 1  (matnorm(eu) @ w2 -> relu -> @w3 + eu) ----------------
// Epilogue uses the multi-value butterfly: 62 SHFL for {h, h^2} instead of 320.
__global__ __launch_bounds__(128) void dense1_kernel(const float* __restrict__ w2, const float* __restrict__ b2,
                                                     const float* __restrict__ w3, const float* __restrict__ b3) {
    const int t = threadIdx.x;
    const int lane = t & 31;
    const int n = blockIdx.y;
    const int pos = blockIdx.x * 128 + t;
    __shared__ float sw2[1024], sw3[1024], sb2[32], sb3[32];
    __shared__ float meanS[22], isdS[22], em3S[10];
    __shared__ float acc1[32], acc2[32];
    for (int i = t; i < 1024; i += 128) { sw2[i] = w2[i]; sw3[i] = w3[i]; }
    if (t < 32) { sb2[t] = b2[t]; sb3[t] = b3[t]; acc1[t] = 0.f; acc2[t] = 0.f; }
    if (t < 22) {
        float mu = g_eusum[n * 22 + t] * (1.f / 4096.f);
        float var = fmaxf(g_eusq[n * 22 + t] * (1.f / 4096.f) - mu * mu, 0.f);
        meanS[t] = mu;
        isdS[t] = 1.f / fmaxf(sqrtf(var), 1e-3f);   // matnorm: clamp OUTSIDE sqrt
    }
    if (t < 10) em3S[t] = g_em3[t];
    __syncthreads();

    float eu[32];
    #pragma unroll
    for (int c = 0; c < 22; ++c) eu[c] = g_lbuf[((size_t)n * 22 + c) * 4096 + pos];
    #pragma unroll
    for (int c = 22; c < 32; ++c) eu[c] = em3S[c - 22];
    float mt[22];
    #pragma unroll
    for (int c = 0; c < 22; ++c) mt[c] = (eu[c] - meanS[c]) * isdS[c];
    // matnorm of the constant embedding channels is exactly 0 (std clamped), so skip c>=22
    float res[32];
    #pragma unroll
    for (int o = 0; o < 32; ++o) {
        float a = sb2[o];
        #pragma unroll
        for (int c = 0; c < 22; ++c) a += mt[c] * sw2[c * 32 + o];
        res[o] = fmaxf(a, 0.f);
    }
    float hq[32];
    #pragma unroll
    for (int o = 0; o < 32; ++o) {
        float a = sb3[o];
        #pragma unroll
        for (int c = 0; c < 32; ++c) a += res[c] * sw3[c * 32 + o];
        float h = eu[o] + a;
        g_h2[((size_t)n * 32 + o) * 4096 + pos] = h;
        eu[o] = h;          // in-place: eu becomes h for the butterfly
        hq[o] = h * h;
    }
    // multi-value butterfly: lane l ends with channel-l sums in eu[0], hq[0]
    #pragma unroll
    for (int off = 16; off; off >>= 1) {
        bool up = (lane & off) != 0;
        #pragma unroll
        for (int c = 0; c < off; ++c) {
            float g1 = up ? eu[c] : eu[c + off];
            float g2 = up ? hq[c] : hq[c + off];
            float r1 = __shfl_xor_sync(0xffffffffu, g1, off);
            float r2 = __shfl_xor_sync(0xffffffffu, g2, off);
            eu[c] = (up ? eu[c + off] : eu[c]) + r1;
            hq[c] = (up ? hq[c + off] : hq[c]) + r2;
        }
    }
    atomicAdd(&acc1[lane], eu[0]);
    atomicAdd(&acc2[lane], hq[0]);
    __syncthreads();
    if (t < 32) {
        atomicAdd(&g_h2sum[n * 32 + t], acc1[t]);
        atomicAdd(&g_h2sq[n * 32 + t], acc2[t]);
    }
}

// ---------------- K3: block 2  (matnorm(h2) @ w4 -> relu -> @w5 + h2, mean) ----------------
// Epilogue uses the multi-value butterfly: 31 SHFL instead of 160.
__global__ __launch_bounds__(128) void dense2_kernel(const float* __restrict__ w4, const float* __restrict__ b4,
                                                     const float* __restrict__ w5, const float* __restrict__ b5) {
    const int t = threadIdx.x;
    const int lane = t & 31;
    const int n = blockIdx.y;
    const int pos = blockIdx.x * 128 + t;
    __shared__ float sw4[1024], sw5[1024], sb4[32], sb5[32];
    __shared__ float meanS[32], isdS[32];
    __shared__ float acc1[32];
    for (int i = t; i < 1024; i += 128) { sw4[i] = w4[i]; sw5[i] = w5[i]; }
    if (t < 32) {
        sb4[t] = b4[t]; sb5[t] = b5[t]; acc1[t] = 0.f;
        float mu = g_h2sum[n * 32 + t] * (1.f / 4096.f);
        float var = fmaxf(g_h2sq[n * 32 + t] * (1.f / 4096.f) - mu * mu, 0.f);
        meanS[t] = mu;
        isdS[t] = 1.f / fmaxf(sqrtf(var), 1e-3f);
    }
    __syncthreads();

    float hv[32];
    #pragma unroll
    for (int c = 0; c < 32; ++c) hv[c] = g_h2[((size_t)n * 32 + c) * 4096 + pos];
    float mt[32];
    #pragma unroll
    for (int c = 0; c < 32; ++c) mt[c] = (hv[c] - meanS[c]) * isdS[c];
    float res[32];
    #pragma unroll
    for (int o = 0; o < 32; ++o) {
        float a = sb4[o];
        #pragma unroll
        for (int c = 0; c < 32; ++c) a += mt[c] * sw4[c * 32 + o];
        res[o] = fmaxf(a, 0.f);
    }
    #pragma unroll
    for (int o = 0; o < 32; ++o) {
        float a = sb5[o];
        #pragma unroll
        for (int c = 0; c < 32; ++c) a += res[c] * sw5[c * 32 + o];
        hv[o] += a;       // h3 value, in place
    }
    // multi-value butterfly: lane l ends with channel-l sum in hv[0]
    #pragma unroll
    for (int off = 16; off; off >>= 1) {
        bool up = (lane & off) != 0;
        #pragma unroll
        for (int c = 0; c < off; ++c) {
            float g1 = up ? hv[c] : hv[c + off];
            float r1 = __shfl_xor_sync(0xffffffffu, g1, off);
            hv[c] = (up ? hv[c + off] : hv[c]) + r1;
        }
    }
    atomicAdd(&acc1[lane], hv[0]);
    __syncthreads();
    if (t < 32) atomicAdd(&g_cov3[n * 32 + t], acc1[t]);
}

// ---------------- K4: head (cov3 @ w -> softmax) ----------------
__global__ void head_kernel(const float* __restrict__ w, float* __restrict__ out) {
    const int n = threadIdx.x;  // 256 threads
    float c[32];
    #pragma unroll
    for (int ch = 0; ch < 32; ++ch) c[ch] = g_cov3[n * 32 + ch] * (1.f / 4096.f);
    float lg[7];
    #pragma unroll
    for (int cls = 0; cls < 7; ++cls) {
        float a = 0.f;
        #pragma unroll
        for (int ch = 0; ch < 32; ++ch) a += c[ch] * w[ch * 7 + cls];
        lg[cls] = a;
    }
    float mx = lg[0];
    #pragma unroll
    for (int cls = 1; cls < 7; ++cls) mx = fmaxf(mx, lg[cls]);
    float sum = 0.f;
    #pragma unroll
    for (int cls = 0; cls < 7; ++cls) { lg[cls] = expf(lg[cls] - mx); sum += lg[cls]; }
    float inv = 1.f / sum;
    #pragma unroll
    for (int cls = 0; cls < 7; ++cls) out[n * 7 + cls] = lg[cls] * inv;
}

// ---------------- launch ----------------
extern "C" void kernel_launch(void* const* d_in, const int* in_sizes, int n_in,
                              void* d_out, int out_size) {
    const float* x   = (const float*)d_in[0];
    const void*  M   = d_in[1];
    const float* w   = (const float*)d_in[2];
    const float* w2  = (const float*)d_in[3];
    const float* b2  = (const float*)d_in[4];
    const float* w3  = (const float*)d_in[5];
    const float* b3  = (const float*)d_in[6];
    const float* w4  = (const float*)d_in[7];
    const float* b4  = (const float*)d_in[8];
    const float* w5  = (const float*)d_in[9];
    const float* b5  = (const float*)d_in[10];
    const float* we1 = (const float*)d_in[11];
    const float* be1 = (const float*)d_in[12];
    const float* we2 = (const float*)d_in[13];
    const float* be2 = (const float*)d_in[14];
    const float* we3 = (const float*)d_in[15];
    const float* be3 = (const float*)d_in[16];
    const float* lng = (const float*)d_in[17];
    const float* lnb = (const float*)d_in[18];

    init_kernel<<<1, 256>>>(M, we1, be1, we2, be2, we3, be3, lng, lnb);
    eig_kernel<<<256 * 22, 128>>>(x);
    dense1_kernel<<<dim3(32, 256), 128>>>(w2, b2, w3, b3);
    dense2_kernel<<<dim3(32, 256), 128>>>(w4, b4, w5, b5);
    head_kernel<<<1, 256>>>(w, (float*)d_out);
}

// round 17
// speedup vs baseline: 1.4845x; 1.1083x over previous
#include <cuda_runtime.h>
#include <cuda_bf16.h>
#include <math.h>

// ---------------- scratch (static device globals; no allocation) ----------------
__device__ float g_lbuf[256 * 22 * 4096];   // log-eig planes, layout [n][ch][pos]
__device__ float g_h2[256 * 32 * 4096];     // h2, layout [n][ch][pos]
__device__ float g_eusum[256 * 22];
__device__ float g_eusq[256 * 22];
__device__ float g_h2sum[256 * 32];
__device__ float g_h2sq[256 * 32];
__device__ float g_cov3[256 * 32];
__device__ float g_em3[10];

#define MAXSWEEPS 10
#define UPAD 68   // U column stride (floats); 16B-aligned

typedef unsigned long long ull;

// ---- packed f32x2 helpers (sm_103a; ptxas only emits FFMA2 via PTX) ----
__device__ __forceinline__ ull f2mul(ull a, ull b) {
    ull d; asm("mul.rn.f32x2 %0, %1, %2;" : "=l"(d) : "l"(a), "l"(b)); return d;
}
__device__ __forceinline__ ull f2fma(ull a, ull b, ull c) {
    ull d; asm("fma.rn.f32x2 %0, %1, %2, %3;" : "=l"(d) : "l"(a), "l"(b), "l"(c)); return d;
}
__device__ __forceinline__ ull f2pack(float lo, float hi) {
    ull d; asm("mov.b64 %0, {%1, %2};" : "=l"(d) : "f"(lo), "f"(hi)); return d;
}
__device__ __forceinline__ float2 f2unpack(ull v) {
    float lo, hi; asm("mov.b64 {%0, %1}, %2;" : "=f"(lo), "=f"(hi) : "l"(v));
    return make_float2(lo, hi);
}

// round-robin pairing: round r in [0,63), pair k in [0,32)
__device__ __forceinline__ void pairpq(int r, int k, int& p, int& q) {
    if (k == 0) { p = 63; q = r; }
    else {
        p = r + k; if (p >= 63) p -= 63;
        q = r - k; if (q < 0)  q += 63;
    }
}

// ---------------- K0: init accumulators + scalar-embedding MLP ----------------
__global__ void init_kernel(const void* __restrict__ Mraw,
                            const float* __restrict__ we1, const float* __restrict__ be1,
                            const float* __restrict__ we2, const float* __restrict__ be2,
                            const float* __restrict__ we3, const float* __restrict__ be3,
                            const float* __restrict__ ln_g, const float* __restrict__ ln_b) {
    const int t = threadIdx.x;  // 256 threads, 1 block
    for (int i = t; i < 256 * 32; i += 256) {
        g_h2sum[i] = 0.f; g_h2sq[i] = 0.f; g_cov3[i] = 0.f;
    }
    __shared__ float md[2];
    __shared__ float em[10], emln[10], em2[100];
    __shared__ float mu_s, isd_s;
    if (t == 0) {
        int mi = *(const int*)Mraw;
        float Mv = (mi > 0 && mi < 100000000) ? (float)mi : __int_as_float(mi);
        md[0] = Mv / 500.0f;
        md[1] = 64.0f / 100.0f;
    }
    __syncthreads();
    if (t < 10) em[t] = md[0] * we1[t] + md[1] * we1[10 + t] + be1[t];
    __syncthreads();
    if (t == 0) {
        float s = 0.f, s2 = 0.f;
        for (int j = 0; j < 10; ++j) { s += em[j]; s2 += em[j] * em[j]; }
        float mu = s * 0.1f;
        float var = fmaxf(s2 * 0.1f - mu * mu, 0.f);
        mu_s = mu;
        isd_s = rsqrtf(var + 1e-3f);   // keras LN: eps inside sqrt
    }
    __syncthreads();
    if (t < 10) emln[t] = (em[t] - mu_s) * isd_s * ln_g[t] + ln_b[t];
    __syncthreads();
    if (t < 100) {
        float a = be2[t];
        for (int j = 0; j < 10; ++j) a += emln[j] * we2[j * 100 + t];
        em2[t] = fmaxf(a, 0.f);
    }
    __syncthreads();
    if (t < 10) {
        float a = be3[t];
        for (int k = 0; k < 100; ++k) a += em2[k] * we3[k * 10 + t];
        g_em3[t] = em[t] + a;
    }
}

// ---------------- K1: shifted one-sided Jacobi (128-thr CTAs, quarter-warp pairs) --
// U = A + sigma*I (PD), column-major (stride UPAD). 16 quarter-warps each
// handle 2 of the 32 pairs per round, in smem with packed f32x2 math.
// lambda_c = ||u_c|| - sigma; L = sum_c (f_c/||u_c||^2) u_c u_c^T.
__global__ __launch_bounds__(128, 10) void eig_kernel(const float* __restrict__ x) {
    __shared__ __align__(16) float U[64 * UPAD];
    __shared__ float nrm[64];
    __shared__ float gsc[64];
    __shared__ float wred[8];
    __shared__ float sig_s, sig2_s;
    __shared__ int conv_s;

    const int t = threadIdx.x;
    const int warp = t >> 5, lane = t & 31;
    const int b = blockIdx.x;      // n*22 + ch
    const float* src = x + (size_t)b * 4096;

    // load plane (coalesced) into U column-major
    #pragma unroll
    for (int it = 0; it < 32; ++it) {
        int id = t + 128 * it;
        int r_ = id >> 6, c_ = id & 63;
        U[c_ * UPAD + r_] = src[id];
    }
    __syncthreads();
    // symmetrize in smem + Frobenius norm^2
    float fn = 0.f;
    #pragma unroll
    for (int it = 0; it < 32; ++it) {
        int id = t + 128 * it;
        int i = id >> 6, j = id & 63;
        if (i < j) {
            float a = 0.5f * (U[i * UPAD + j] + U[j * UPAD + i]);
            U[i * UPAD + j] = a; U[j * UPAD + i] = a;
            fn += 2.f * a * a;
        } else if (i == j) {
            float d = U[i * UPAD + i];
            fn += d * d;
        }
    }
    #pragma unroll
    for (int off = 16; off; off >>= 1) fn += __shfl_xor_sync(0xffffffffu, fn, off);
    if (lane == 0) wred[warp] = fn;
    __syncthreads();
    if (t == 0) {
        float s = wred[0] + wred[1] + wred[2] + wred[3];
        sig2_s = s;
        sig_s = sqrtf(s);
        conv_s = 0;
    }
    __syncthreads();
    const float sigma = sig_s;
    if (t < 64) U[t * UPAD + t] += sigma;   // shift: U = A + sigma*I  (PD)
    __syncthreads();
    // initial column sq-norms (one-time)
    if (t < 64) {
        const float* uc = U + t * UPAD;
        float s = 0.f;
        #pragma unroll 8
        for (int r_ = 0; r_ < 64; ++r_) { float v = uc[r_]; s += v * v; }
        nrm[t] = s;
    }
    __syncthreads();

    const float skipthr = 2e-4f * sig2_s + 1e-30f;
    const float convthr = 8e-3f * sig2_s + 1e-30f;

    const int ql = lane & 7;                   // lane within quarter
    const int qid = (warp << 2) | (lane >> 3); // quarter id 0..15

    for (int sweep = 0; sweep < MAXSWEEPS; ++sweep) {
        float swmax = 0.f;
        for (int r = 0; r < 63; ++r) {
            #pragma unroll
            for (int j = 0; j < 2; ++j) {
                int k = (qid << 1) | j;
                int p, q; pairpq(r, k, p, q);
                ulonglong2* Up = (ulonglong2*)(U + p * UPAD);
                ulonglong2* Uq = (ulonglong2*)(U + q * UPAD);
                ulonglong2 A0 = Up[ql], A1 = Up[ql + 8];
                ulonglong2 B0 = Uq[ql], B1 = Uq[ql + 8];
                ull acc = f2mul(A0.x, B0.x);
                acc = f2fma(A0.y, B0.y, acc);
                acc = f2fma(A1.x, B1.x, acc);
                acc = f2fma(A1.y, B1.y, acc);
                float2 ac = f2unpack(acc);
                float spq = ac.x + ac.y;
                #pragma unroll
                for (int off = 4; off; off >>= 1)
                    spq += __shfl_xor_sync(0xffffffffu, spq, off);
                swmax = fmaxf(swmax, fabsf(spq));
                if (fabsf(spq) > skipthr) {
                    float dpp = nrm[p], dqq = nrm[q];
                    float tau = (dqq - dpp) / (2.f * spq);
                    float tt = copysignf(1.f, tau) / (fabsf(tau) + sqrtf(1.f + tau * tau));
                    float c = rsqrtf(1.f + tt * tt);
                    float s = tt * c;
                    ull c2 = f2pack(c, c), s2 = f2pack(s, s), ns2 = f2pack(-s, -s);
                    ulonglong2 N0, N1, M0, M1;
                    N0.x = f2fma(A0.x, c2, f2mul(B0.x, ns2));
                    N0.y = f2fma(A0.y, c2, f2mul(B0.y, ns2));
                    N1.x = f2fma(A1.x, c2, f2mul(B1.x, ns2));
                    N1.y = f2fma(A1.y, c2, f2mul(B1.y, ns2));
                    M0.x = f2fma(A0.x, s2, f2mul(B0.x, c2));
                    M0.y = f2fma(A0.y, s2, f2mul(B0.y, c2));
                    M1.x = f2fma(A1.x, s2, f2mul(B1.x, c2));
                    M1.y = f2fma(A1.y, s2, f2mul(B1.y, c2));
                    Up[ql] = N0; Up[ql + 8] = N1;
                    Uq[ql] = M0; Uq[ql + 8] = M1;
                    if (ql == 0) {
                        float cc = c * c, ss = s * s, cs2 = 2.f * c * s * spq;
                        nrm[p] = cc * dpp + ss * dqq - cs2;
                        nrm[q] = ss * dpp + cc * dqq + cs2;
                    }
                }
            }
            __syncthreads();
        }
        // merge quarters' swmax, then block-reduce
        swmax = fmaxf(swmax, __shfl_xor_sync(0xffffffffu, swmax, 8));
        swmax = fmaxf(swmax, __shfl_xor_sync(0xffffffffu, swmax, 16));
        if (lane == 0) wred[warp] = swmax;
        __syncthreads();
        if (t == 0) {
            float m = fmaxf(fmaxf(wred[0], wred[1]), fmaxf(wred[2], wred[3]));
            conv_s = (m < convthr) ? 1 : 0;
        }
        __syncthreads();
        if (conv_s) break;
    }

    // exact column norms (double), lambda = ||u|| - sigma, scale g = f/||u||^2
    if (t < 64) {
        const float* uc = U + t * UPAD;
        double s = 0.0;
        #pragma unroll 8
        for (int r_ = 0; r_ < 64; ++r_) { double v = (double)uc[r_]; s += v * v; }
        double rho = sqrt(s);
        float lam = (float)(rho - (double)sigma);
        float f = logf(fmaxf(lam, 1e-4f));
        gsc[t] = (float)((double)f / s);
    }
    __syncthreads();

    // L[i][j] = sum_m gsc[m] * U[m][i] * U[m][j]
    // Vectorized: LDS.128 row chunks + FFMA2 accumulation + STG.128 stores.
    const int i0 = t >> 1;
    float lsum = 0.f, lsq = 0.f;
    float* dst = g_lbuf + (size_t)b * 4096;
    #pragma unroll
    for (int chunk = 0; chunk < 2; ++chunk) {
        const int j0 = ((t & 1) << 5) + (chunk << 4);
        ull acc[8];
        #pragma unroll
        for (int jj = 0; jj < 8; ++jj) acc[jj] = 0ull;
        #pragma unroll 2
        for (int m = 0; m < 64; ++m) {
            float a = gsc[m] * U[m * UPAD + i0];
            ull aa = f2pack(a, a);
            const ulonglong2* ur = (const ulonglong2*)(U + m * UPAD + j0);
            ulonglong2 r0 = ur[0], r1 = ur[1];
            acc[0] = f2fma(aa, r0.x, acc[0]);
            acc[1] = f2fma(aa, r0.y, acc[1]);
            acc[2] = f2fma(aa, r1.x, acc[2]);
            acc[3] = f2fma(aa, r1.y, acc[3]);
            acc[4] = f2fma(aa, ur[2].x, acc[4]);
            acc[5] = f2fma(aa, ur[2].y, acc[5]);
            acc[6] = f2fma(aa, ur[3].x, acc[6]);
            acc[7] = f2fma(aa, ur[3].y, acc[7]);
        }
        ulonglong2* d2 = (ulonglong2*)(dst + i0 * 64 + j0);
        #pragma unroll
        for (int k = 0; k < 4; ++k) {
            d2[k] = make_ulonglong2(acc[2 * k], acc[2 * k + 1]);
            float2 u0 = f2unpack(acc[2 * k]), u1 = f2unpack(acc[2 * k + 1]);
            lsum += u0.x + u0.y + u1.x + u1.y;
            lsq  += u0.x * u0.x + u0.y * u0.y + u1.x * u1.x + u1.y * u1.y;
        }
    }
    #pragma unroll
    for (int off = 16; off; off >>= 1) {
        lsum += __shfl_down_sync(0xffffffffu, lsum, off);
        lsq  += __shfl_down_sync(0xffffffffu, lsq, off);
    }
    if (lane == 0) { wred[warp] = lsum; wred[4 + warp] = lsq; }
    __syncthreads();
    if (t == 0) {
        g_eusum[b] = wred[0] + wred[1] + wred[2] + wred[3];
        g_eusq[b]  = wred[4] + wred[5] + wred[6] + wred[7];
    }
}

// ---------------- K2: block 1  (matnorm(eu) @ w2 -> relu -> @w3 + eu) ----------------
// Epilogue uses the multi-value butterfly: 62 SHFL for {h, h^2} instead of 320.
__global__ __launch_bounds__(128) void dense1_kernel(const float* __restrict__ w2, const float* __restrict__ b2,
                                                     const float* __restrict__ w3, const float* __restrict__ b3) {
    const int t = threadIdx.x;
    const int lane = t & 31;
    const int n = blockIdx.y;
    const int pos = blockIdx.x * 128 + t;
    __shared__ float sw2[1024], sw3[1024], sb2[32], sb3[32];
    __shared__ float meanS[22], isdS[22], em3S[10];
    __shared__ float acc1[32], acc2[32];
    for (int i = t; i < 1024; i += 128) { sw2[i] = w2[i]; sw3[i] = w3[i]; }
    if (t < 32) { sb2[t] = b2[t]; sb3[t] = b3[t]; acc1[t] = 0.f; acc2[t] = 0.f; }
    if (t < 22) {
        float mu = g_eusum[n * 22 + t] * (1.f / 4096.f);
        float var = fmaxf(g_eusq[n * 22 + t] * (1.f / 4096.f) - mu * mu, 0.f);
        meanS[t] = mu;
        isdS[t] = 1.f / fmaxf(sqrtf(var), 1e-3f);   // matnorm: clamp OUTSIDE sqrt
    }
    if (t < 10) em3S[t] = g_em3[t];
    __syncthreads();

    float eu[32];
    #pragma unroll
    for (int c = 0; c < 22; ++c) eu[c] = g_lbuf[((size_t)n * 22 + c) * 4096 + pos];
    #pragma unroll
    for (int c = 22; c < 32; ++c) eu[c] = em3S[c - 22];
    float mt[22];
    #pragma unroll
    for (int c = 0; c < 22; ++c) mt[c] = (eu[c] - meanS[c]) * isdS[c];
    // matnorm of the constant embedding channels is exactly 0 (std clamped), so skip c>=22
    float res[32];
    #pragma unroll
    for (int o = 0; o < 32; ++o) {
        float a = sb2[o];
        #pragma unroll
        for (int c = 0; c < 22; ++c) a += mt[c] * sw2[c * 32 + o];
        res[o] = fmaxf(a, 0.f);
    }
    float hq[32];
    #pragma unroll
    for (int o = 0; o < 32; ++o) {
        float a = sb3[o];
        #pragma unroll
        for (int c = 0; c < 32; ++c) a += res[c] * sw3[c * 32 + o];
        float h = eu[o] + a;
        g_h2[((size_t)n * 32 + o) * 4096 + pos] = h;
        eu[o] = h;          // in-place: eu becomes h for the butterfly
        hq[o] = h * h;
    }
    // multi-value butterfly: lane l ends with channel-l sums in eu[0], hq[0]
    #pragma unroll
    for (int off = 16; off; off >>= 1) {
        bool up = (lane & off) != 0;
        #pragma unroll
        for (int c = 0; c < off; ++c) {
            float g1 = up ? eu[c] : eu[c + off];
            float g2 = up ? hq[c] : hq[c + off];
            float r1 = __shfl_xor_sync(0xffffffffu, g1, off);
            float r2 = __shfl_xor_sync(0xffffffffu, g2, off);
            eu[c] = (up ? eu[c + off] : eu[c]) + r1;
            hq[c] = (up ? hq[c + off] : hq[c]) + r2;
        }
    }
    atomicAdd(&acc1[lane], eu[0]);
    atomicAdd(&acc2[lane], hq[0]);
    __syncthreads();
    if (t < 32) {
        atomicAdd(&g_h2sum[n * 32 + t], acc1[t]);
        atomicAdd(&g_h2sq[n * 32 + t], acc2[t]);
    }
}

// ---------------- K3: block 2  (matnorm(h2) @ w4 -> relu -> @w5 + h2, mean) ----------------
// Epilogue uses the multi-value butterfly: 31 SHFL instead of 160.
__global__ __launch_bounds__(128) void dense2_kernel(const float* __restrict__ w4, const float* __restrict__ b4,
                                                     const float* __restrict__ w5, const float* __restrict__ b5) {
    const int t = threadIdx.x;
    const int lane = t & 31;
    const int n = blockIdx.y;
    const int pos = blockIdx.x * 128 + t;
    __shared__ float sw4[1024], sw5[1024], sb4[32], sb5[32];
    __shared__ float meanS[32], isdS[32];
    __shared__ float acc1[32];
    for (int i = t; i < 1024; i += 128) { sw4[i] = w4[i]; sw5[i] = w5[i]; }
    if (t < 32) {
        sb4[t] = b4[t]; sb5[t] = b5[t]; acc1[t] = 0.f;
        float mu = g_h2sum[n * 32 + t] * (1.f / 4096.f);
        float var = fmaxf(g_h2sq[n * 32 + t] * (1.f / 4096.f) - mu * mu, 0.f);
        meanS[t] = mu;
        isdS[t] = 1.f / fmaxf(sqrtf(var), 1e-3f);
    }
    __syncthreads();

    float hv[32];
    #pragma unroll
    for (int c = 0; c < 32; ++c) hv[c] = g_h2[((size_t)n * 32 + c) * 4096 + pos];
    float mt[32];
    #pragma unroll
    for (int c = 0; c < 32; ++c) mt[c] = (hv[c] - meanS[c]) * isdS[c];
    float res[32];
    #pragma unroll
    for (int o = 0; o < 32; ++o) {
        float a = sb4[o];
        #pragma unroll
        for (int c = 0; c < 32; ++c) a += mt[c] * sw4[c * 32 + o];
        res[o] = fmaxf(a, 0.f);
    }
    #pragma unroll
    for (int o = 0; o < 32; ++o) {
        float a = sb5[o];
        #pragma unroll
        for (int c = 0; c < 32; ++c) a += res[c] * sw5[c * 32 + o];
        hv[o] += a;       // h3 value, in place
    }
    // multi-value butterfly: lane l ends with channel-l sum in hv[0]
    #pragma unroll
    for (int off = 16; off; off >>= 1) {
        bool up = (lane & off) != 0;
        #pragma unroll
        for (int c = 0; c < off; ++c) {
            float g1 = up ? hv[c] : hv[c + off];
            float r1 = __shfl_xor_sync(0xffffffffu, g1, off);
            hv[c] = (up ? hv[c + off] : hv[c]) + r1;
        }
    }
    atomicAdd(&acc1[lane], hv[0]);
    __syncthreads();
    if (t < 32) atomicAdd(&g_cov3[n * 32 + t], acc1[t]);
}

// ---------------- K4: head (cov3 @ w -> softmax) ----------------
__global__ void head_kernel(const float* __restrict__ w, float* __restrict__ out) {
    const int n = threadIdx.x;  // 256 threads
    float c[32];
    #pragma unroll
    for (int ch = 0; ch < 32; ++ch) c[ch] = g_cov3[n * 32 + ch] * (1.f / 4096.f);
    float lg[7];
    #pragma unroll
    for (int cls = 0; cls < 7; ++cls) {
        float a = 0.f;
        #pragma unroll
        for (int ch = 0; ch < 32; ++ch) a += c[ch] * w[ch * 7 + cls];
        lg[cls] = a;
    }
    float mx = lg[0];
    #pragma unroll
    for (int cls = 1; cls < 7; ++cls) mx = fmaxf(mx, lg[cls]);
    float sum = 0.f;
    #pragma unroll
    for (int cls = 0; cls < 7; ++cls) { lg[cls] = expf(lg[cls] - mx); sum += lg[cls]; }
    float inv = 1.f / sum;
    #pragma unroll
    for (int cls = 0; cls < 7; ++cls) out[n * 7 + cls] = lg[cls] * inv;
}

// ---------------- launch ----------------
extern "C" void kernel_launch(void* const* d_in, const int* in_sizes, int n_in,
                              void* d_out, int out_size) {
    const float* x   = (const float*)d_in[0];
    const void*  M   = d_in[1];
    const float* w   = (const float*)d_in[2];
    const float* w2  = (const float*)d_in[3];
    const float* b2  = (const float*)d_in[4];
    const float* w3  = (const float*)d_in[5];
    const float* b3  = (const float*)d_in[6];
    const float* w4  = (const float*)d_in[7];
    const float* b4  = (const float*)d_in[8];
    const float* w5  = (const float*)d_in[9];
    const float* b5  = (const float*)d_in[10];
    const float* we1 = (const float*)d_in[11];
    const float* be1 = (const float*)d_in[12];
    const float* we2 = (const float*)d_in[13];
    const float* be2 = (const float*)d_in[14];
    const float* we3 = (const float*)d_in[15];
    const float* be3 = (const float*)d_in[16];
    const float* lng = (const float*)d_in[17];
    const float* lnb = (const float*)d_in[18];

    init_kernel<<<1, 256>>>(M, we1, be1, we2, be2, we3, be3, lng, lnb);
    eig_kernel<<<256 * 22, 128>>>(x);
    dense1_kernel<<<dim3(32, 256), 128>>>(w2, b2, w3, b3);
    dense2_kernel<<<dim3(32, 256), 128>>>(w4, b4, w5, b5);
    head_kernel<<<1, 256>>>(w, (float*)d_out);
}